// round 2
// baseline (speedup 1.0000x reference)
#include <cuda_runtime.h>
#include <math.h>
#include <stdint.h>

// ---------------- problem constants ----------------
#define BSZ   512
#define LSZ   160     // L == R == 160
#define DDIM  350
#define DP    352     // padded D (zero pad cols 350,351)
#define NCH   600     // stacked conv output channels (6 x 100)
#define NPAD  640     // padded N for GEMM tiles of 64

// ---------------- device scratch (globals: allocation-free rule) ----------------
__device__ float g_lvec[(size_t)BSZ * LSZ * DP];     // [b][l][dp]
__device__ float g_rvec[(size_t)BSZ * LSZ * DP];     // [b][r][dp]
__device__ float g_att [(size_t)BSZ * LSZ * LSZ];    // [b][l][r]
__device__ float g_attT[(size_t)BSZ * LSZ * LSZ];    // [b][r][l]
__device__ float g_lc  [(size_t)BSZ * LSZ * DP];     // [b][t][dp]
__device__ float g_rc  [(size_t)BSZ * LSZ * DP];
__device__ float g_Zl  [(size_t)BSZ * LSZ * NCH];    // [b][t][600]
__device__ float g_Zr  [(size_t)BSZ * LSZ * NCH];
__device__ float g_wall[(size_t)NPAD * DP];          // [n][k] stacked filters
__device__ float g_feats[(size_t)BSZ * NCH];         // [b][600]

// ---------------- build stacked filter matrix ----------------
__global__ void prep_wall_kernel(const float* __restrict__ w1,
                                 const float* __restrict__ w2,
                                 const float* __restrict__ w3) {
    int idx = blockIdx.x * blockDim.x + threadIdx.x;
    if (idx >= NPAD * DP) return;
    int n = idx / DP, k = idx % DP;
    float v = 0.f;
    if (k < DDIM && n < NCH) {
        if      (n < 100) v = w1[n * DDIM + k];                       // conv1 tau0
        else if (n < 200) v = w2[(n - 100) * (DDIM * 2) + k * 2 + 0]; // conv2 tau0
        else if (n < 300) v = w2[(n - 200) * (DDIM * 2) + k * 2 + 1]; // conv2 tau1
        else if (n < 400) v = w3[(n - 300) * (DDIM * 3) + k * 3 + 0]; // conv3 tau0
        else if (n < 500) v = w3[(n - 400) * (DDIM * 3) + k * 3 + 1]; // conv3 tau1
        else              v = w3[(n - 500) * (DDIM * 3) + k * 3 + 2]; // conv3 tau2
    }
    g_wall[idx] = v;
}

// ---------------- embedding gather: [attr(50) | word(300)] ----------------
__global__ void gather_kernel(const int* __restrict__ lt, const int* __restrict__ la,
                              const int* __restrict__ rt, const int* __restrict__ ra,
                              const float* __restrict__ wemb, const float* __restrict__ aemb) {
    int l = blockIdx.x, b = blockIdx.y, side = blockIdx.z;
    const int* tok = side ? rt : lt;
    const int* atr = side ? ra : la;
    float* dst = (side ? g_rvec : g_lvec) + ((size_t)(b * LSZ + l)) * DP;
    int t = tok[l * BSZ + b];
    int a = atr[l * BSZ + b];
    const float* wr = wemb + (size_t)t * 300;
    const float* ar = aemb + (size_t)a * 50;
    for (int d = threadIdx.x; d < DP; d += blockDim.x) {
        float v = 0.f;
        if (d < 50) v = ar[d];
        else if (d < DDIM) v = wr[d - 50];
        dst[d] = v;
    }
}

// ---------------- batched attention GEMM: att[b] = lvec[b] * rvec[b]^T ----------------
// 64x64 tile, 256 threads, 4x4 micro-tile, K=352 (no guards, zero-padded).
__global__ void att_gemm_kernel(const int* __restrict__ llen, const int* __restrict__ rlen) {
    int b  = blockIdx.z;
    int m0 = blockIdx.x * 64;   // l
    int n0 = blockIdx.y * 64;   // r
    if (m0 >= llen[b] || n0 >= rlen[b]) return;

    const float* A  = g_lvec + (size_t)b * LSZ * DP;
    const float* Bv = g_rvec + (size_t)b * LSZ * DP;

    __shared__ float Xs[16][64];
    __shared__ float Ws[16][64];
    __shared__ float Ts[64][68];

    int tid = threadIdx.x;
    int tx = tid & 15, ty = tid >> 4;
    int lrow = tid & 63;
    int lk   = (tid >> 6) * 4;

    float acc[4][4];
#pragma unroll
    for (int i = 0; i < 4; i++)
#pragma unroll
        for (int j = 0; j < 4; j++) acc[i][j] = 0.f;

    for (int k0 = 0; k0 < DP; k0 += 16) {
        float4 xv = make_float4(0.f, 0.f, 0.f, 0.f);
        float4 wv = make_float4(0.f, 0.f, 0.f, 0.f);
        int gm = m0 + lrow;
        int gn = n0 + lrow;
        if (gm < LSZ) xv = *(const float4*)(A  + (size_t)gm * DP + k0 + lk);
        if (gn < LSZ) wv = *(const float4*)(Bv + (size_t)gn * DP + k0 + lk);
        Xs[lk + 0][lrow] = xv.x; Xs[lk + 1][lrow] = xv.y;
        Xs[lk + 2][lrow] = xv.z; Xs[lk + 3][lrow] = xv.w;
        Ws[lk + 0][lrow] = wv.x; Ws[lk + 1][lrow] = wv.y;
        Ws[lk + 2][lrow] = wv.z; Ws[lk + 3][lrow] = wv.w;
        __syncthreads();
#pragma unroll
        for (int kk = 0; kk < 16; kk++) {
            float4 a4 = *(const float4*)&Xs[kk][ty * 4];
            float4 b4 = *(const float4*)&Ws[kk][tx * 4];
            acc[0][0] += a4.x * b4.x; acc[0][1] += a4.x * b4.y; acc[0][2] += a4.x * b4.z; acc[0][3] += a4.x * b4.w;
            acc[1][0] += a4.y * b4.x; acc[1][1] += a4.y * b4.y; acc[1][2] += a4.y * b4.z; acc[1][3] += a4.y * b4.w;
            acc[2][0] += a4.z * b4.x; acc[2][1] += a4.z * b4.y; acc[2][2] += a4.z * b4.z; acc[2][3] += a4.z * b4.w;
            acc[3][0] += a4.w * b4.x; acc[3][1] += a4.w * b4.y; acc[3][2] += a4.w * b4.z; acc[3][3] += a4.w * b4.w;
        }
        __syncthreads();
    }

    // write att[b][l][r]
#pragma unroll
    for (int i = 0; i < 4; i++) {
        int gm = m0 + ty * 4 + i;
        int gn = n0 + tx * 4;
        if (gm < LSZ && gn < LSZ) {
            float4 o = make_float4(acc[i][0], acc[i][1], acc[i][2], acc[i][3]);
            *(float4*)(g_att + ((size_t)b * LSZ + gm) * LSZ + gn) = o;
        }
    }
    // transpose through smem, write attT[b][r][l]
    __syncthreads();
#pragma unroll
    for (int i = 0; i < 4; i++)
#pragma unroll
        for (int j = 0; j < 4; j++) Ts[tx * 4 + j][ty * 4 + i] = acc[i][j];
    __syncthreads();
    int rr  = tid >> 2;
    int cc0 = (tid & 3) * 16;
    int r = n0 + rr;
    if (r < LSZ) {
#pragma unroll
        for (int q = 0; q < 4; q++) {
            int c = cc0 + q * 4;
            int gl = m0 + c;
            if (gl < LSZ)
                *(float4*)(g_attT + ((size_t)b * LSZ + r) * LSZ + gl) = *(const float4*)&Ts[rr][c];
        }
    }
}

// ---------------- fused softmax / stats / top-3 / counterpart ----------------
__device__ __forceinline__ bool tk_better(float av, int ai, float bv, int bi) {
    return (av > bv) || (av == bv && ai < bi);
}
__device__ __forceinline__ void tk_insert(float nv, int ni,
                                          float& v0, int& i0, float& v1, int& i1, float& v2, int& i2) {
    if (tk_better(nv, ni, v0, i0)) { v2 = v1; i2 = i1; v1 = v0; i1 = i0; v0 = nv; i0 = ni; }
    else if (tk_better(nv, ni, v1, i1)) { v2 = v1; i2 = i1; v1 = nv; i1 = ni; }
    else if (tk_better(nv, ni, v2, i2)) { v2 = nv; i2 = ni; }
}

__global__ void attproc_kernel(const int* __restrict__ ll, const int* __restrict__ rl) {
    int side = blockIdx.y;
    const float* attRows  = side ? g_attT : g_att;
    const float* vecSelf  = side ? g_rvec : g_lvec;
    const float* vecOther = side ? g_lvec : g_rvec;
    const int* lenSelf    = side ? rl : ll;
    const int* lenOther   = side ? ll : rl;
    float* cOut           = side ? g_rc : g_lc;

    int wid  = blockIdx.x * (blockDim.x >> 5) + (threadIdx.x >> 5);
    int lane = threadIdx.x & 31;
    int b = wid / LSZ, i = wid % LSZ;
    if (b >= BSZ) return;
    if (i >= lenSelf[b]) return;          // row never read downstream
    int n = lenOther[b];
    const float* row = attRows + ((size_t)b * LSZ + i) * LSZ;
    const unsigned FULL = 0xffffffffu;

    // pass 1: top-3 on raw scores (softmax is monotone)
    float v0 = -3.0e38f, v1 = -3.0e38f, v2 = -3.0e38f;
    int i0 = 0x7fffffff, i1 = 0x7fffffff, i2 = 0x7fffffff;
    for (int j = lane; j < n; j += 32) {
        float a = row[j];
        tk_insert(a, j, v0, i0, v1, i1, v2, i2);
    }
#pragma unroll
    for (int off = 16; off >= 1; off >>= 1) {
        float ov0 = __shfl_xor_sync(FULL, v0, off);
        int   oi0 = __shfl_xor_sync(FULL, i0, off);
        float ov1 = __shfl_xor_sync(FULL, v1, off);
        int   oi1 = __shfl_xor_sync(FULL, i1, off);
        float ov2 = __shfl_xor_sync(FULL, v2, off);
        int   oi2 = __shfl_xor_sync(FULL, i2, off);
        tk_insert(ov0, oi0, v0, i0, v1, i1, v2, i2);
        tk_insert(ov1, oi1, v0, i0, v1, i1, v2, i2);
        tk_insert(ov2, oi2, v0, i0, v1, i1, v2, i2);
    }
    float m = v0;  // row max over valid entries

    // pass 2: softmax denominator and sum of squares
    float S = 0.f, S2 = 0.f;
    for (int j = lane; j < n; j += 32) {
        float e = expf(row[j] - m);
        S += e; S2 += e * e;
    }
#pragma unroll
    for (int off = 16; off >= 1; off >>= 1) {
        S  += __shfl_xor_sync(FULL, S,  off);
        S2 += __shfl_xor_sync(FULL, S2, off);
    }

    float rlenf = (float)n;
    float mean  = 1.0f / rlenf;              // sum of softmax == 1
    float s2    = S2 / (S * S);
    float w     = (s2 / rlenf - mean * mean) / fmaxf(mean, 0.001f);

    float a0 = 1.0f, a1 = expf(v1 - v0), a2 = expf(v2 - v0);
    float asum = a0 + a1 + a2;               // >= 3/n > 0.001, clamp never fires
    a0 /= asum; a1 /= asum; a2 /= asum;

    const float* g0 = vecOther + ((size_t)b * LSZ + i0) * DP;
    const float* g1 = vecOther + ((size_t)b * LSZ + i1) * DP;
    const float* g2 = vecOther + ((size_t)b * LSZ + i2) * DP;
    const float* sv = vecSelf  + ((size_t)b * LSZ + i) * DP;
    float* dst      = cOut     + ((size_t)b * LSZ + i) * DP;
    for (int d = lane; d < DP; d += 32) {
        float val = 0.f;
        if (d < DDIM) {
            float ctr = a0 * g0[d] + a1 * g1[d] + a2 * g2[d];
            val = w * fabsf(sv[d] - ctr);
        }
        dst[d] = val;
    }
}

// ---------------- conv GEMM: Z[b][t][0..599] = X[b][t][:] * Wall^T ----------------
__global__ void conv_gemm_kernel(const int* __restrict__ llen, const int* __restrict__ rlen) {
    int zb = blockIdx.z;
    int side = zb >> 9, b = zb & 511;
    int m0 = blockIdx.x * 64;   // t
    int n0 = blockIdx.y * 64;   // channel
    int len = side ? rlen[b] : llen[b];
    if (m0 >= len) return;      // Z rows >= len are never read

    const float* X = (side ? g_rc : g_lc) + (size_t)b * LSZ * DP;
    float* Zo      = (side ? g_Zr : g_Zl) + (size_t)b * LSZ * NCH;

    __shared__ float Xs[16][64];
    __shared__ float Ws[16][64];

    int tid = threadIdx.x;
    int tx = tid & 15, ty = tid >> 4;
    int lrow = tid & 63;
    int lk   = (tid >> 6) * 4;

    float acc[4][4];
#pragma unroll
    for (int i = 0; i < 4; i++)
#pragma unroll
        for (int j = 0; j < 4; j++) acc[i][j] = 0.f;

    for (int k0 = 0; k0 < DP; k0 += 16) {
        float4 xv = make_float4(0.f, 0.f, 0.f, 0.f);
        int gm = m0 + lrow;
        if (gm < LSZ) xv = *(const float4*)(X + (size_t)gm * DP + k0 + lk);
        float4 wv = *(const float4*)(g_wall + (size_t)(n0 + lrow) * DP + k0 + lk);
        Xs[lk + 0][lrow] = xv.x; Xs[lk + 1][lrow] = xv.y;
        Xs[lk + 2][lrow] = xv.z; Xs[lk + 3][lrow] = xv.w;
        Ws[lk + 0][lrow] = wv.x; Ws[lk + 1][lrow] = wv.y;
        Ws[lk + 2][lrow] = wv.z; Ws[lk + 3][lrow] = wv.w;
        __syncthreads();
#pragma unroll
        for (int kk = 0; kk < 16; kk++) {
            float4 a4 = *(const float4*)&Xs[kk][ty * 4];
            float4 b4 = *(const float4*)&Ws[kk][tx * 4];
            acc[0][0] += a4.x * b4.x; acc[0][1] += a4.x * b4.y; acc[0][2] += a4.x * b4.z; acc[0][3] += a4.x * b4.w;
            acc[1][0] += a4.y * b4.x; acc[1][1] += a4.y * b4.y; acc[1][2] += a4.y * b4.z; acc[1][3] += a4.y * b4.w;
            acc[2][0] += a4.z * b4.x; acc[2][1] += a4.z * b4.y; acc[2][2] += a4.z * b4.z; acc[2][3] += a4.z * b4.w;
            acc[3][0] += a4.w * b4.x; acc[3][1] += a4.w * b4.y; acc[3][2] += a4.w * b4.z; acc[3][3] += a4.w * b4.w;
        }
        __syncthreads();
    }

#pragma unroll
    for (int i = 0; i < 4; i++) {
        int gm = m0 + ty * 4 + i;
        int gn = n0 + tx * 4;
        if (gm < LSZ && gn < NCH) {
            float4 o = make_float4(acc[i][0], acc[i][1], acc[i][2], acc[i][3]);
            *(float4*)(Zo + (size_t)gm * NCH + gn) = o;
        }
    }
}

// ---------------- masked relu-max pooling over positions ----------------
__global__ void combine_kernel(const int* __restrict__ llen, const int* __restrict__ rlen,
                               const float* __restrict__ cb1, const float* __restrict__ cb2,
                               const float* __restrict__ cb3) {
    int b = blockIdx.x, side = blockIdx.y;
    const float* Z = (side ? g_Zr : g_Zl) + (size_t)b * LSZ * NCH;
    int len = side ? rlen[b] : llen[b];
    int j = threadIdx.x;
    if (j >= 300) return;
    float mx = -1e30f;
    if (j < 100) {
        float bias = cb1[j];
        for (int t = 0; t <= len - 1; t++) {
            float s = Z[(size_t)t * NCH + j] + bias;
            mx = fmaxf(mx, fmaxf(s, 0.f));
        }
    } else if (j < 200) {
        int o = j - 100; float bias = cb2[o];
        for (int t = 0; t <= len - 2; t++) {
            float s = Z[(size_t)t * NCH + 100 + o] + Z[(size_t)(t + 1) * NCH + 200 + o] + bias;
            mx = fmaxf(mx, fmaxf(s, 0.f));
        }
    } else {
        int o = j - 200; float bias = cb3[o];
        for (int t = 0; t <= len - 3; t++) {
            float s = Z[(size_t)t * NCH + 300 + o] + Z[(size_t)(t + 1) * NCH + 400 + o]
                    + Z[(size_t)(t + 2) * NCH + 500 + o] + bias;
            mx = fmaxf(mx, fmaxf(s, 0.f));
        }
    }
    g_feats[(size_t)b * NCH + side * 300 + j] = mx;
}

// ---------------- dense head ----------------
__global__ void dense_kernel(const float* __restrict__ dw1, const float* __restrict__ db1,
                             const float* __restrict__ dw2, const float* __restrict__ db2,
                             float* __restrict__ out) {
    int b = blockIdx.x;
    __shared__ float f[NCH];
    __shared__ float h[64];
    int tid = threadIdx.x;
    for (int j = tid; j < NCH; j += blockDim.x) f[j] = g_feats[(size_t)b * NCH + j];
    __syncthreads();
    if (tid < 60) {
        float s = db1[tid];
        for (int j = 0; j < NCH; j++) s += f[j] * dw1[j * 60 + tid];
        h[tid] = fmaxf(s, 0.f);
    }
    __syncthreads();
    if (tid < 2) {
        float s = db2[tid];
        for (int j = 0; j < 60; j++) s += h[j] * dw2[j * 2 + tid];
        out[b * 2 + tid] = s;
    }
}

// ---------------- launch ----------------
extern "C" void kernel_launch(void* const* d_in, const int* in_sizes, int n_in,
                              void* d_out, int out_size) {
    const int*   lt   = (const int*)d_in[0];
    const int*   la   = (const int*)d_in[1];
    const int*   ll   = (const int*)d_in[2];
    const int*   rt   = (const int*)d_in[3];
    const int*   ra   = (const int*)d_in[4];
    const int*   rl   = (const int*)d_in[5];
    const float* wemb = (const float*)d_in[6];
    const float* aemb = (const float*)d_in[7];
    const float* cw1  = (const float*)d_in[8];
    const float* cb1  = (const float*)d_in[9];
    const float* cw2  = (const float*)d_in[10];
    const float* cb2  = (const float*)d_in[11];
    const float* cw3  = (const float*)d_in[12];
    const float* cb3  = (const float*)d_in[13];
    const float* dw1  = (const float*)d_in[14];
    const float* db1  = (const float*)d_in[15];
    const float* dw2  = (const float*)d_in[16];
    const float* db2  = (const float*)d_in[17];
    float* out = (float*)d_out;

    prep_wall_kernel<<<(NPAD * DP + 255) / 256, 256>>>(cw1, cw2, cw3);
    gather_kernel<<<dim3(LSZ, BSZ, 2), 128>>>(lt, la, rt, ra, wemb, aemb);
    att_gemm_kernel<<<dim3(3, 3, BSZ), 256>>>(ll, rl);
    attproc_kernel<<<dim3((BSZ * LSZ) / 4, 2), 128>>>(ll, rl);
    conv_gemm_kernel<<<dim3(3, 10, 2 * BSZ), 256>>>(ll, rl);
    combine_kernel<<<dim3(BSZ, 2), 320>>>(ll, rl, cb1, cb2, cb3);
    dense_kernel<<<BSZ, 128>>>(dw1, db1, dw2, db2, out);
}

// round 3
// speedup vs baseline: 1.1758x; 1.1758x over previous
#include <cuda_runtime.h>
#include <math.h>
#include <stdint.h>

// ---------------- problem constants ----------------
#define BSZ   512
#define LSZ   160     // L == R == 160
#define DDIM  350
#define DP    352     // padded D (zero pad cols 350,351)
#define NCH   600     // stacked conv output channels (6 x 100)
#define NPAD  640     // padded N for GEMM tiles of 64
#define SKP   36      // smem row pitch (32 k + 4 pad)

// ---------------- device scratch (globals: allocation-free rule) ----------------
__device__ float g_lvec[(size_t)BSZ * LSZ * DP];     // [b][l][dp]
__device__ float g_rvec[(size_t)BSZ * LSZ * DP];     // [b][r][dp]
__device__ float g_att [(size_t)BSZ * LSZ * LSZ];    // [b][l][r]
__device__ float g_attT[(size_t)BSZ * LSZ * LSZ];    // [b][r][l]
__device__ float g_lc  [(size_t)BSZ * LSZ * DP];     // [b][t][dp]
__device__ float g_rc  [(size_t)BSZ * LSZ * DP];
__device__ float g_Zl  [(size_t)BSZ * LSZ * NCH];    // [b][t][600]
__device__ float g_Zr  [(size_t)BSZ * LSZ * NCH];
__device__ float g_wall[(size_t)NPAD * DP];          // [n][k] stacked filters
__device__ float g_feats[(size_t)BSZ * NCH];         // [b][600]

// ---------------- tf32 helpers ----------------
__device__ __forceinline__ unsigned f2tf(float x) {
    unsigned u;
    asm("cvt.rna.tf32.f32 %0, %1;" : "=r"(u) : "f"(x));
    return u;
}
__device__ __forceinline__ void split_tf(float x, unsigned& hi, unsigned& lo) {
    hi = f2tf(x);
    float h = __uint_as_float(hi);
    lo = f2tf(x - h);
}
__device__ __forceinline__ void mma8(float* c, const unsigned* a, unsigned b0, unsigned b1) {
    asm volatile(
        "mma.sync.aligned.m16n8k8.row.col.f32.tf32.tf32.f32 "
        "{%0,%1,%2,%3}, {%4,%5,%6,%7}, {%8,%9}, {%0,%1,%2,%3};"
        : "+f"(c[0]), "+f"(c[1]), "+f"(c[2]), "+f"(c[3])
        : "r"(a[0]), "r"(a[1]), "r"(a[2]), "r"(a[3]), "r"(b0), "r"(b1));
}

// ---------------- build stacked filter matrix ----------------
__global__ void prep_wall_kernel(const float* __restrict__ w1,
                                 const float* __restrict__ w2,
                                 const float* __restrict__ w3) {
    int idx = blockIdx.x * blockDim.x + threadIdx.x;
    if (idx >= NPAD * DP) return;
    int n = idx / DP, k = idx % DP;
    float v = 0.f;
    if (k < DDIM && n < NCH) {
        if      (n < 100) v = w1[n * DDIM + k];
        else if (n < 200) v = w2[(n - 100) * (DDIM * 2) + k * 2 + 0];
        else if (n < 300) v = w2[(n - 200) * (DDIM * 2) + k * 2 + 1];
        else if (n < 400) v = w3[(n - 300) * (DDIM * 3) + k * 3 + 0];
        else if (n < 500) v = w3[(n - 400) * (DDIM * 3) + k * 3 + 1];
        else              v = w3[(n - 500) * (DDIM * 3) + k * 3 + 2];
    }
    g_wall[idx] = v;
}

// ---------------- embedding gather: [attr(50) | word(300)] ----------------
__global__ void gather_kernel(const int* __restrict__ lt, const int* __restrict__ la,
                              const int* __restrict__ rt, const int* __restrict__ ra,
                              const float* __restrict__ wemb, const float* __restrict__ aemb) {
    int l = blockIdx.x, b = blockIdx.y, side = blockIdx.z;
    const int* tok = side ? rt : lt;
    const int* atr = side ? ra : la;
    float* dst = (side ? g_rvec : g_lvec) + ((size_t)(b * LSZ + l)) * DP;
    int t = tok[l * BSZ + b];
    int a = atr[l * BSZ + b];
    const float* wr = wemb + (size_t)t * 300;
    const float* ar = aemb + (size_t)a * 50;
    for (int d = threadIdx.x; d < DP; d += blockDim.x) {
        float v = 0.f;
        if (d < 50) v = ar[d];
        else if (d < DDIM) v = wr[d - 50];
        dst[d] = v;
    }
}

// =====================================================================
// Split-tf32 tensor-core GEMM bodies. 64x64 tile, 256 threads = 8 warps
// (4m x 2n warp grid, 16x32 warp tiles), K-block 32 (4 k8 steps),
// 3-term split: acc += xh*wh + xh*wl + xl*wh   (fp32-equivalent accuracy)
// =====================================================================

// smem carve: Xh | Xl | Wh | Wl, each 64*SKP uints = 9216B; total 36864B
#define SM_XH 0
#define SM_XL (64 * SKP)
#define SM_WH (2 * 64 * SKP)
#define SM_WL (3 * 64 * SKP)

// ---------------- attention GEMM: att[b] = lvec[b] * rvec[b]^T ----------------
__global__ void att_gemm_kernel(const int* __restrict__ llen, const int* __restrict__ rlen) {
    __shared__ unsigned sb[4 * 64 * SKP];
    int b  = blockIdx.z;
    int m0 = blockIdx.x * 64;   // l
    int n0 = blockIdx.y * 64;   // r
    if (m0 >= llen[b] || n0 >= rlen[b]) return;

    const float* A  = g_lvec + (size_t)b * LSZ * DP;
    const float* Bv = g_rvec + (size_t)b * LSZ * DP;

    int tid  = threadIdx.x;
    int lane = tid & 31;
    int wid  = tid >> 5;
    int wm   = wid & 3;         // 0..3 (m)
    int wn   = wid >> 2;        // 0..1 (n)

    int lrow = tid >> 2;        // 0..63
    int lkq  = (tid & 3) * 8;   // 0,8,16,24

    float acc[4][4];
#pragma unroll
    for (int i = 0; i < 4; i++)
#pragma unroll
        for (int j = 0; j < 4; j++) acc[i][j] = 0.f;

    for (int k0 = 0; k0 < DP; k0 += 32) {
        // load 8 floats of A row and 8 of B row per thread, split to tf32 hi/lo
        int gm = m0 + lrow, gn = n0 + lrow;
#pragma unroll
        for (int h = 0; h < 2; h++) {
            int kk = lkq + h * 4;
            float4 xv = make_float4(0.f, 0.f, 0.f, 0.f);
            float4 wv = make_float4(0.f, 0.f, 0.f, 0.f);
            if (gm < LSZ) xv = *(const float4*)(A  + (size_t)gm * DP + k0 + kk);
            if (gn < LSZ) wv = *(const float4*)(Bv + (size_t)gn * DP + k0 + kk);
            unsigned hi, lo;
            int base = lrow * SKP + kk;
            split_tf(xv.x, hi, lo); sb[SM_XH + base + 0] = hi; sb[SM_XL + base + 0] = lo;
            split_tf(xv.y, hi, lo); sb[SM_XH + base + 1] = hi; sb[SM_XL + base + 1] = lo;
            split_tf(xv.z, hi, lo); sb[SM_XH + base + 2] = hi; sb[SM_XL + base + 2] = lo;
            split_tf(xv.w, hi, lo); sb[SM_XH + base + 3] = hi; sb[SM_XL + base + 3] = lo;
            split_tf(wv.x, hi, lo); sb[SM_WH + base + 0] = hi; sb[SM_WL + base + 0] = lo;
            split_tf(wv.y, hi, lo); sb[SM_WH + base + 1] = hi; sb[SM_WL + base + 1] = lo;
            split_tf(wv.z, hi, lo); sb[SM_WH + base + 2] = hi; sb[SM_WL + base + 2] = lo;
            split_tf(wv.w, hi, lo); sb[SM_WH + base + 3] = hi; sb[SM_WL + base + 3] = lo;
        }
        __syncthreads();
#pragma unroll
        for (int ks = 0; ks < 4; ks++) {
            int k = ks * 8;
            int r0 = wm * 16 + (lane >> 2);
            int c  = lane & 3;
            unsigned ah[4], al[4];
            ah[0] = sb[SM_XH + r0 * SKP + k + c];
            ah[1] = sb[SM_XH + (r0 + 8) * SKP + k + c];
            ah[2] = sb[SM_XH + r0 * SKP + k + 4 + c];
            ah[3] = sb[SM_XH + (r0 + 8) * SKP + k + 4 + c];
            al[0] = sb[SM_XL + r0 * SKP + k + c];
            al[1] = sb[SM_XL + (r0 + 8) * SKP + k + c];
            al[2] = sb[SM_XL + r0 * SKP + k + 4 + c];
            al[3] = sb[SM_XL + (r0 + 8) * SKP + k + 4 + c];
#pragma unroll
            for (int nf = 0; nf < 4; nf++) {
                int cn = wn * 32 + nf * 8 + (lane >> 2);
                unsigned bh0 = sb[SM_WH + cn * SKP + k + c];
                unsigned bh1 = sb[SM_WH + cn * SKP + k + 4 + c];
                unsigned bl0 = sb[SM_WL + cn * SKP + k + c];
                unsigned bl1 = sb[SM_WL + cn * SKP + k + 4 + c];
                mma8(acc[nf], ah, bh0, bh1);
                mma8(acc[nf], ah, bl0, bl1);
                mma8(acc[nf], al, bh0, bh1);
            }
        }
        __syncthreads();
    }

    // stage result tile in smem (aliased over operand buffers)
    float* Ts = (float*)sb;    // [64][68]
#pragma unroll
    for (int nf = 0; nf < 4; nf++) {
        int r0 = wm * 16 + (lane >> 2);
        int cn = wn * 32 + nf * 8 + 2 * (lane & 3);
        Ts[r0 * 68 + cn]           = acc[nf][0];
        Ts[r0 * 68 + cn + 1]       = acc[nf][1];
        Ts[(r0 + 8) * 68 + cn]     = acc[nf][2];
        Ts[(r0 + 8) * 68 + cn + 1] = acc[nf][3];
    }
    __syncthreads();

    // coalesced write of att[b][l][r]
    {
        int row = tid >> 2;
        int gm = m0 + row;
        if (gm < LSZ) {
#pragma unroll
            for (int q = 0; q < 4; q++) {
                int cl = (tid & 3) * 16 + q * 4;
                int gn = n0 + cl;
                if (gn < LSZ)
                    *(float4*)(g_att + ((size_t)b * LSZ + gm) * LSZ + gn) =
                        *(const float4*)&Ts[row * 68 + cl];
            }
        }
    }
    // coalesced write of attT[b][r][l]
    {
        int rr = tid >> 2;
        int gr = n0 + rr;
        if (gr < LSZ) {
#pragma unroll
            for (int q = 0; q < 4; q++) {
                int l0 = (tid & 3) * 16 + q * 4;
                int gl = m0 + l0;
                if (gl < LSZ) {
                    float4 o;
                    o.x = Ts[(l0 + 0) * 68 + rr];
                    o.y = Ts[(l0 + 1) * 68 + rr];
                    o.z = Ts[(l0 + 2) * 68 + rr];
                    o.w = Ts[(l0 + 3) * 68 + rr];
                    *(float4*)(g_attT + ((size_t)b * LSZ + gr) * LSZ + gl) = o;
                }
            }
        }
    }
}

// ---------------- fused softmax / stats / top-3 / counterpart ----------------
__device__ __forceinline__ bool tk_better(float av, int ai, float bv, int bi) {
    return (av > bv) || (av == bv && ai < bi);
}
__device__ __forceinline__ void tk_insert(float nv, int ni,
                                          float& v0, int& i0, float& v1, int& i1, float& v2, int& i2) {
    if (tk_better(nv, ni, v0, i0)) { v2 = v1; i2 = i1; v1 = v0; i1 = i0; v0 = nv; i0 = ni; }
    else if (tk_better(nv, ni, v1, i1)) { v2 = v1; i2 = i1; v1 = nv; i1 = ni; }
    else if (tk_better(nv, ni, v2, i2)) { v2 = nv; i2 = ni; }
}

__global__ void attproc_kernel(const int* __restrict__ ll, const int* __restrict__ rl) {
    int side = blockIdx.y;
    const float* attRows  = side ? g_attT : g_att;
    const float* vecSelf  = side ? g_rvec : g_lvec;
    const float* vecOther = side ? g_lvec : g_rvec;
    const int* lenSelf    = side ? rl : ll;
    const int* lenOther   = side ? ll : rl;
    float* cOut           = side ? g_rc : g_lc;

    int wid  = blockIdx.x * (blockDim.x >> 5) + (threadIdx.x >> 5);
    int lane = threadIdx.x & 31;
    int b = wid / LSZ, i = wid % LSZ;
    if (b >= BSZ) return;
    if (i >= lenSelf[b]) return;
    int n = lenOther[b];
    const float* row = attRows + ((size_t)b * LSZ + i) * LSZ;
    const unsigned FULL = 0xffffffffu;

    float v0 = -3.0e38f, v1 = -3.0e38f, v2 = -3.0e38f;
    int i0 = 0x7fffffff, i1 = 0x7fffffff, i2 = 0x7fffffff;
    for (int j = lane; j < n; j += 32) {
        float a = row[j];
        tk_insert(a, j, v0, i0, v1, i1, v2, i2);
    }
#pragma unroll
    for (int off = 16; off >= 1; off >>= 1) {
        float ov0 = __shfl_xor_sync(FULL, v0, off);
        int   oi0 = __shfl_xor_sync(FULL, i0, off);
        float ov1 = __shfl_xor_sync(FULL, v1, off);
        int   oi1 = __shfl_xor_sync(FULL, i1, off);
        float ov2 = __shfl_xor_sync(FULL, v2, off);
        int   oi2 = __shfl_xor_sync(FULL, i2, off);
        tk_insert(ov0, oi0, v0, i0, v1, i1, v2, i2);
        tk_insert(ov1, oi1, v0, i0, v1, i1, v2, i2);
        tk_insert(ov2, oi2, v0, i0, v1, i1, v2, i2);
    }
    float m = v0;

    float S = 0.f, S2 = 0.f;
    for (int j = lane; j < n; j += 32) {
        float e = expf(row[j] - m);
        S += e; S2 += e * e;
    }
#pragma unroll
    for (int off = 16; off >= 1; off >>= 1) {
        S  += __shfl_xor_sync(FULL, S,  off);
        S2 += __shfl_xor_sync(FULL, S2, off);
    }

    float rlenf = (float)n;
    float mean  = 1.0f / rlenf;
    float s2    = S2 / (S * S);
    float w     = (s2 / rlenf - mean * mean) / fmaxf(mean, 0.001f);

    float a0 = 1.0f, a1 = expf(v1 - v0), a2 = expf(v2 - v0);
    float asum = a0 + a1 + a2;
    a0 /= asum; a1 /= asum; a2 /= asum;

    const float* g0 = vecOther + ((size_t)b * LSZ + i0) * DP;
    const float* g1 = vecOther + ((size_t)b * LSZ + i1) * DP;
    const float* g2 = vecOther + ((size_t)b * LSZ + i2) * DP;
    const float* sv = vecSelf  + ((size_t)b * LSZ + i) * DP;
    float* dst      = cOut     + ((size_t)b * LSZ + i) * DP;
    for (int d = lane; d < DP; d += 32) {
        float val = 0.f;
        if (d < DDIM) {
            float ctr = a0 * g0[d] + a1 * g1[d] + a2 * g2[d];
            val = w * fabsf(sv[d] - ctr);
        }
        dst[d] = val;
    }
}

// ---------------- conv GEMM: Z[b][t][:] = X[b][t][:] * Wall^T (split-tf32) --------
__global__ void conv_gemm_kernel(const int* __restrict__ llen, const int* __restrict__ rlen) {
    __shared__ unsigned sb[4 * 64 * SKP];
    int zb = blockIdx.z;
    int side = zb >> 9, b = zb & 511;
    int m0 = blockIdx.x * 64;   // t
    int n0 = blockIdx.y * 64;   // channel
    int len = side ? rlen[b] : llen[b];
    if (m0 >= len) return;

    const float* X = (side ? g_rc : g_lc) + (size_t)b * LSZ * DP;
    float* Zo      = (side ? g_Zr : g_Zl) + (size_t)b * LSZ * NCH;

    int tid  = threadIdx.x;
    int lane = tid & 31;
    int wid  = tid >> 5;
    int wm   = wid & 3;
    int wn   = wid >> 2;

    int lrow = tid >> 2;
    int lkq  = (tid & 3) * 8;

    float acc[4][4];
#pragma unroll
    for (int i = 0; i < 4; i++)
#pragma unroll
        for (int j = 0; j < 4; j++) acc[i][j] = 0.f;

    for (int k0 = 0; k0 < DP; k0 += 32) {
        int gm = m0 + lrow;
#pragma unroll
        for (int h = 0; h < 2; h++) {
            int kk = lkq + h * 4;
            float4 xv = make_float4(0.f, 0.f, 0.f, 0.f);
            if (gm < LSZ) xv = *(const float4*)(X + (size_t)gm * DP + k0 + kk);
            float4 wv = *(const float4*)(g_wall + (size_t)(n0 + lrow) * DP + k0 + kk);
            unsigned hi, lo;
            int base = lrow * SKP + kk;
            split_tf(xv.x, hi, lo); sb[SM_XH + base + 0] = hi; sb[SM_XL + base + 0] = lo;
            split_tf(xv.y, hi, lo); sb[SM_XH + base + 1] = hi; sb[SM_XL + base + 1] = lo;
            split_tf(xv.z, hi, lo); sb[SM_XH + base + 2] = hi; sb[SM_XL + base + 2] = lo;
            split_tf(xv.w, hi, lo); sb[SM_XH + base + 3] = hi; sb[SM_XL + base + 3] = lo;
            split_tf(wv.x, hi, lo); sb[SM_WH + base + 0] = hi; sb[SM_WL + base + 0] = lo;
            split_tf(wv.y, hi, lo); sb[SM_WH + base + 1] = hi; sb[SM_WL + base + 1] = lo;
            split_tf(wv.z, hi, lo); sb[SM_WH + base + 2] = hi; sb[SM_WL + base + 2] = lo;
            split_tf(wv.w, hi, lo); sb[SM_WH + base + 3] = hi; sb[SM_WL + base + 3] = lo;
        }
        __syncthreads();
#pragma unroll
        for (int ks = 0; ks < 4; ks++) {
            int k = ks * 8;
            int r0 = wm * 16 + (lane >> 2);
            int c  = lane & 3;
            unsigned ah[4], al[4];
            ah[0] = sb[SM_XH + r0 * SKP + k + c];
            ah[1] = sb[SM_XH + (r0 + 8) * SKP + k + c];
            ah[2] = sb[SM_XH + r0 * SKP + k + 4 + c];
            ah[3] = sb[SM_XH + (r0 + 8) * SKP + k + 4 + c];
            al[0] = sb[SM_XL + r0 * SKP + k + c];
            al[1] = sb[SM_XL + (r0 + 8) * SKP + k + c];
            al[2] = sb[SM_XL + r0 * SKP + k + 4 + c];
            al[3] = sb[SM_XL + (r0 + 8) * SKP + k + 4 + c];
#pragma unroll
            for (int nf = 0; nf < 4; nf++) {
                int cn = wn * 32 + nf * 8 + (lane >> 2);
                unsigned bh0 = sb[SM_WH + cn * SKP + k + c];
                unsigned bh1 = sb[SM_WH + cn * SKP + k + 4 + c];
                unsigned bl0 = sb[SM_WL + cn * SKP + k + c];
                unsigned bl1 = sb[SM_WL + cn * SKP + k + 4 + c];
                mma8(acc[nf], ah, bh0, bh1);
                mma8(acc[nf], ah, bl0, bl1);
                mma8(acc[nf], al, bh0, bh1);
            }
        }
        __syncthreads();
    }

    // direct global stores (Z layout [t][600])
    int r0 = wm * 16 + (lane >> 2);
#pragma unroll
    for (int nf = 0; nf < 4; nf++) {
        int gn = n0 + wn * 32 + nf * 8 + 2 * (lane & 3);
        if (gn < NCH) {
            int gm = m0 + r0;
            if (gm < LSZ)
                *(float2*)(Zo + (size_t)gm * NCH + gn) = make_float2(acc[nf][0], acc[nf][1]);
            gm += 8;
            if (gm < LSZ)
                *(float2*)(Zo + (size_t)gm * NCH + gn) = make_float2(acc[nf][2], acc[nf][3]);
        }
    }
}

// ---------------- masked relu-max pooling over positions ----------------
__global__ void combine_kernel(const int* __restrict__ llen, const int* __restrict__ rlen,
                               const float* __restrict__ cb1, const float* __restrict__ cb2,
                               const float* __restrict__ cb3) {
    int b = blockIdx.x, side = blockIdx.y;
    const float* Z = (side ? g_Zr : g_Zl) + (size_t)b * LSZ * NCH;
    int len = side ? rlen[b] : llen[b];
    int j = threadIdx.x;
    if (j >= 300) return;
    float mx = -1e30f;
    if (j < 100) {
        float bias = cb1[j];
        for (int t = 0; t <= len - 1; t++) {
            float s = Z[(size_t)t * NCH + j] + bias;
            mx = fmaxf(mx, fmaxf(s, 0.f));
        }
    } else if (j < 200) {
        int o = j - 100; float bias = cb2[o];
        for (int t = 0; t <= len - 2; t++) {
            float s = Z[(size_t)t * NCH + 100 + o] + Z[(size_t)(t + 1) * NCH + 200 + o] + bias;
            mx = fmaxf(mx, fmaxf(s, 0.f));
        }
    } else {
        int o = j - 200; float bias = cb3[o];
        for (int t = 0; t <= len - 3; t++) {
            float s = Z[(size_t)t * NCH + 300 + o] + Z[(size_t)(t + 1) * NCH + 400 + o]
                    + Z[(size_t)(t + 2) * NCH + 500 + o] + bias;
            mx = fmaxf(mx, fmaxf(s, 0.f));
        }
    }
    g_feats[(size_t)b * NCH + side * 300 + j] = mx;
}

// ---------------- dense head ----------------
__global__ void dense_kernel(const float* __restrict__ dw1, const float* __restrict__ db1,
                             const float* __restrict__ dw2, const float* __restrict__ db2,
                             float* __restrict__ out) {
    int b = blockIdx.x;
    __shared__ float f[NCH];
    __shared__ float h[64];
    int tid = threadIdx.x;
    for (int j = tid; j < NCH; j += blockDim.x) f[j] = g_feats[(size_t)b * NCH + j];
    __syncthreads();
    if (tid < 60) {
        float s = db1[tid];
        for (int j = 0; j < NCH; j++) s += f[j] * dw1[j * 60 + tid];
        h[tid] = fmaxf(s, 0.f);
    }
    __syncthreads();
    if (tid < 2) {
        float s = db2[tid];
        for (int j = 0; j < 60; j++) s += h[j] * dw2[j * 2 + tid];
        out[b * 2 + tid] = s;
    }
}

// ---------------- launch ----------------
extern "C" void kernel_launch(void* const* d_in, const int* in_sizes, int n_in,
                              void* d_out, int out_size) {
    const int*   lt   = (const int*)d_in[0];
    const int*   la   = (const int*)d_in[1];
    const int*   ll   = (const int*)d_in[2];
    const int*   rt   = (const int*)d_in[3];
    const int*   ra   = (const int*)d_in[4];
    const int*   rl   = (const int*)d_in[5];
    const float* wemb = (const float*)d_in[6];
    const float* aemb = (const float*)d_in[7];
    const float* cw1  = (const float*)d_in[8];
    const float* cb1  = (const float*)d_in[9];
    const float* cw2  = (const float*)d_in[10];
    const float* cb2  = (const float*)d_in[11];
    const float* cw3  = (const float*)d_in[12];
    const float* cb3  = (const float*)d_in[13];
    const float* dw1  = (const float*)d_in[14];
    const float* db1  = (const float*)d_in[15];
    const float* dw2  = (const float*)d_in[16];
    const float* db2  = (const float*)d_in[17];
    float* out = (float*)d_out;

    prep_wall_kernel<<<(NPAD * DP + 255) / 256, 256>>>(cw1, cw2, cw3);
    gather_kernel<<<dim3(LSZ, BSZ, 2), 128>>>(lt, la, rt, ra, wemb, aemb);
    att_gemm_kernel<<<dim3(3, 3, BSZ), 256>>>(ll, rl);
    attproc_kernel<<<dim3((BSZ * LSZ) / 4, 2), 128>>>(ll, rl);
    conv_gemm_kernel<<<dim3(3, 10, 2 * BSZ), 256>>>(ll, rl);
    combine_kernel<<<dim3(BSZ, 2), 320>>>(ll, rl, cb1, cb2, cb3);
    dense_kernel<<<BSZ, 128>>>(dw1, db1, dw2, db2, out);
}

// round 4
// speedup vs baseline: 1.8430x; 1.5674x over previous
#include <cuda_runtime.h>
#include <cuda_bf16.h>
#include <math.h>
#include <stdint.h>

// ---------------- problem constants ----------------
#define BSZ   512
#define LSZ   160     // L == R == 160
#define DDIM  350
#define DP    352     // padded D (zero pad cols 350,351)
#define NCH   600     // stacked conv output channels (6 x 100)
#define NPAD  640
#define WP    20      // smem word pitch per row (16 words of bf16x2 + 4 pad)

// ---------------- device scratch ----------------
__device__ float g_lvec[(size_t)BSZ * LSZ * DP];
__device__ float g_rvec[(size_t)BSZ * LSZ * DP];
__device__ float g_att [(size_t)BSZ * LSZ * LSZ];
__device__ float g_attT[(size_t)BSZ * LSZ * LSZ];
__device__ float g_lc  [(size_t)BSZ * LSZ * DP];
__device__ float g_rc  [(size_t)BSZ * LSZ * DP];
__device__ float g_Zl  [(size_t)BSZ * LSZ * NCH];
__device__ float g_Zr  [(size_t)BSZ * LSZ * NCH];
__device__ float g_wall[(size_t)NPAD * DP];
__device__ float g_feats[(size_t)BSZ * NCH];

// ---------------- bf16 split helpers ----------------
// word = {bf16(x_k) in [15:0], bf16(x_{k+1}) in [31:16]}
__device__ __forceinline__ void split2(float a, float b, unsigned& hi, unsigned& lo) {
    __nv_bfloat162 h = __floats2bfloat162_rn(a, b);
    float ra = a - __bfloat162float(h.x);
    float rb = b - __bfloat162float(h.y);
    __nv_bfloat162 l = __floats2bfloat162_rn(ra, rb);
    hi = *(unsigned*)&h;
    lo = *(unsigned*)&l;
}
__device__ __forceinline__ void mma16(float* c, const unsigned* a, unsigned b0, unsigned b1) {
    asm volatile(
        "mma.sync.aligned.m16n8k16.row.col.f32.bf16.bf16.f32 "
        "{%0,%1,%2,%3}, {%4,%5,%6,%7}, {%8,%9}, {%0,%1,%2,%3};"
        : "+f"(c[0]), "+f"(c[1]), "+f"(c[2]), "+f"(c[3])
        : "r"(a[0]), "r"(a[1]), "r"(a[2]), "r"(a[3]), "r"(b0), "r"(b1));
}

// ---------------- build stacked filter matrix ----------------
__global__ void prep_wall_kernel(const float* __restrict__ w1,
                                 const float* __restrict__ w2,
                                 const float* __restrict__ w3) {
    int idx = blockIdx.x * blockDim.x + threadIdx.x;
    if (idx >= NPAD * DP) return;
    int n = idx / DP, k = idx % DP;
    float v = 0.f;
    if (k < DDIM && n < NCH) {
        if      (n < 100) v = w1[n * DDIM + k];
        else if (n < 200) v = w2[(n - 100) * (DDIM * 2) + k * 2 + 0];
        else if (n < 300) v = w2[(n - 200) * (DDIM * 2) + k * 2 + 1];
        else if (n < 400) v = w3[(n - 300) * (DDIM * 3) + k * 3 + 0];
        else if (n < 500) v = w3[(n - 400) * (DDIM * 3) + k * 3 + 1];
        else              v = w3[(n - 500) * (DDIM * 3) + k * 3 + 2];
    }
    g_wall[idx] = v;
}

// ---------------- embedding gather ----------------
__global__ void gather_kernel(const int* __restrict__ lt, const int* __restrict__ la,
                              const int* __restrict__ rt, const int* __restrict__ ra,
                              const float* __restrict__ wemb, const float* __restrict__ aemb) {
    int l = blockIdx.x, b = blockIdx.y, side = blockIdx.z;
    const int* tok = side ? rt : lt;
    const int* atr = side ? ra : la;
    float* dst = (side ? g_rvec : g_lvec) + ((size_t)(b * LSZ + l)) * DP;
    int t = tok[l * BSZ + b];
    int a = atr[l * BSZ + b];
    const float* wr = wemb + (size_t)t * 300;
    const float* ar = aemb + (size_t)a * 50;
    int q = threadIdx.x;           // 0..87 handle float4 slots
    if (q < 88) {
        int d0 = q * 4;
        float4 o;
        float* op = (float*)&o;
#pragma unroll
        for (int c = 0; c < 4; c++) {
            int d = d0 + c;
            float v = 0.f;
            if (d < 50) v = __ldg(ar + d);
            else if (d < DDIM) v = __ldg(wr + d - 50);
            op[c] = v;
        }
        *(float4*)(dst + d0) = o;
    }
}

// =====================================================================
// bf16x2 split tensor GEMM. 64x64 tile, 8 warps (4m x 2n), K-block 32
// (2 x k16 mma steps), 3-term split: acc += xh*wh + xh*wl + xl*wh
// smem: XH|XL|WH|WL, each 64 rows x WP words; total 20480 B
// =====================================================================
#define SM_XH 0
#define SM_XL (64 * WP)
#define SM_WH (2 * 64 * WP)
#define SM_WL (3 * 64 * WP)

struct GemmAcc { float a[4][4]; };

__device__ __forceinline__ void gemm_store_phase(unsigned* sb, const float* Arow, const float* Brow,
                                                 bool aval, bool bval, int lrow, int lkq, int k0) {
#pragma unroll
    for (int h = 0; h < 2; h++) {
        int kk = lkq + h * 4;
        float4 xv = make_float4(0.f, 0.f, 0.f, 0.f);
        float4 wv = make_float4(0.f, 0.f, 0.f, 0.f);
        if (aval) xv = *(const float4*)(Arow + k0 + kk);
        if (bval) wv = *(const float4*)(Brow + k0 + kk);
        unsigned hi, lo;
        int base = lrow * WP + kk / 2;
        split2(xv.x, xv.y, hi, lo); sb[SM_XH + base + 0] = hi; sb[SM_XL + base + 0] = lo;
        split2(xv.z, xv.w, hi, lo); sb[SM_XH + base + 1] = hi; sb[SM_XL + base + 1] = lo;
        split2(wv.x, wv.y, hi, lo); sb[SM_WH + base + 0] = hi; sb[SM_WL + base + 0] = lo;
        split2(wv.z, wv.w, hi, lo); sb[SM_WH + base + 1] = hi; sb[SM_WL + base + 1] = lo;
    }
}

__device__ __forceinline__ void gemm_math_phase(const unsigned* sb, GemmAcc* acc,
                                                int wm, int wn, int lane) {
    int r0 = wm * 16 + (lane >> 2);
    int c  = lane & 3;
#pragma unroll
    for (int ks = 0; ks < 2; ks++) {
        int kw = ks * 8;
        unsigned ah[4], al[4];
        ah[0] = sb[SM_XH + r0 * WP + kw + c];
        ah[1] = sb[SM_XH + (r0 + 8) * WP + kw + c];
        ah[2] = sb[SM_XH + r0 * WP + kw + 4 + c];
        ah[3] = sb[SM_XH + (r0 + 8) * WP + kw + 4 + c];
        al[0] = sb[SM_XL + r0 * WP + kw + c];
        al[1] = sb[SM_XL + (r0 + 8) * WP + kw + c];
        al[2] = sb[SM_XL + r0 * WP + kw + 4 + c];
        al[3] = sb[SM_XL + (r0 + 8) * WP + kw + 4 + c];
#pragma unroll
        for (int nf = 0; nf < 4; nf++) {
            int cn = wn * 32 + nf * 8 + (lane >> 2);
            unsigned bh0 = sb[SM_WH + cn * WP + kw + c];
            unsigned bh1 = sb[SM_WH + cn * WP + kw + 4 + c];
            unsigned bl0 = sb[SM_WL + cn * WP + kw + c];
            unsigned bl1 = sb[SM_WL + cn * WP + kw + 4 + c];
            mma16(acc->a[nf], ah, bh0, bh1);
            mma16(acc->a[nf], ah, bl0, bl1);
            mma16(acc->a[nf], al, bh0, bh1);
        }
    }
}

// ---------------- attention GEMM ----------------
__global__ __launch_bounds__(256) void att_gemm_kernel(const int* __restrict__ llen,
                                                       const int* __restrict__ rlen) {
    __shared__ unsigned sb[4 * 64 * WP];
    __shared__ float Ts[64 * 68];
    int b  = blockIdx.z;
    int m0 = blockIdx.x * 64;
    int n0 = blockIdx.y * 64;
    if (m0 >= llen[b] || n0 >= rlen[b]) return;

    const float* A  = g_lvec + (size_t)b * LSZ * DP;
    const float* Bv = g_rvec + (size_t)b * LSZ * DP;

    int tid  = threadIdx.x;
    int lane = tid & 31;
    int wid  = tid >> 5;
    int wm   = wid & 3, wn = wid >> 2;
    int lrow = tid >> 2;
    int lkq  = (tid & 3) * 8;

    GemmAcc acc;
#pragma unroll
    for (int i = 0; i < 4; i++)
#pragma unroll
        for (int j = 0; j < 4; j++) acc.a[i][j] = 0.f;

    const float* Arow = A  + (size_t)(m0 + lrow) * DP;
    const float* Brow = Bv + (size_t)(n0 + lrow) * DP;
    bool aval = (m0 + lrow) < LSZ;
    bool bval = (n0 + lrow) < LSZ;

    for (int k0 = 0; k0 < DP; k0 += 32) {
        gemm_store_phase(sb, Arow, Brow, aval, bval, lrow, lkq, k0);
        __syncthreads();
        gemm_math_phase(sb, &acc, wm, wn, lane);
        __syncthreads();
    }

    // stage result tile in smem
    {
        int r0 = wm * 16 + (lane >> 2);
        int cb = wn * 32 + 2 * (lane & 3);
#pragma unroll
        for (int nf = 0; nf < 4; nf++) {
            int cn = cb + nf * 8;
            Ts[r0 * 68 + cn]           = acc.a[nf][0];
            Ts[r0 * 68 + cn + 1]       = acc.a[nf][1];
            Ts[(r0 + 8) * 68 + cn]     = acc.a[nf][2];
            Ts[(r0 + 8) * 68 + cn + 1] = acc.a[nf][3];
        }
    }
    __syncthreads();

    {   // att[b][l][r]
        int row = tid >> 2;
        int gm = m0 + row;
        if (gm < LSZ) {
#pragma unroll
            for (int q = 0; q < 4; q++) {
                int cl = (tid & 3) * 16 + q * 4;
                int gn = n0 + cl;
                if (gn < LSZ)
                    *(float4*)(g_att + ((size_t)b * LSZ + gm) * LSZ + gn) =
                        *(const float4*)&Ts[row * 68 + cl];
            }
        }
    }
    {   // attT[b][r][l]
        int rr = tid >> 2;
        int gr = n0 + rr;
        if (gr < LSZ) {
#pragma unroll
            for (int q = 0; q < 4; q++) {
                int l0 = (tid & 3) * 16 + q * 4;
                int gl = m0 + l0;
                if (gl < LSZ) {
                    float4 o;
                    o.x = Ts[(l0 + 0) * 68 + rr];
                    o.y = Ts[(l0 + 1) * 68 + rr];
                    o.z = Ts[(l0 + 2) * 68 + rr];
                    o.w = Ts[(l0 + 3) * 68 + rr];
                    *(float4*)(g_attT + ((size_t)b * LSZ + gr) * LSZ + gl) = o;
                }
            }
        }
    }
}

// ---------------- fused softmax / stats / top-3 / counterpart ----------------
__device__ __forceinline__ bool tk_better(float av, int ai, float bv, int bi) {
    return (av > bv) || (av == bv && ai < bi);
}
__device__ __forceinline__ void tk_insert(float nv, int ni,
                                          float& v0, int& i0, float& v1, int& i1, float& v2, int& i2) {
    if (tk_better(nv, ni, v0, i0)) { v2 = v1; i2 = i1; v1 = v0; i1 = i0; v0 = nv; i0 = ni; }
    else if (tk_better(nv, ni, v1, i1)) { v2 = v1; i2 = i1; v1 = nv; i1 = ni; }
    else if (tk_better(nv, ni, v2, i2)) { v2 = nv; i2 = ni; }
}

__global__ void attproc_kernel(const int* __restrict__ ll, const int* __restrict__ rl) {
    int side = blockIdx.y;
    const float* attRows  = side ? g_attT : g_att;
    const float* vecSelf  = side ? g_rvec : g_lvec;
    const float* vecOther = side ? g_lvec : g_rvec;
    const int* lenSelf    = side ? rl : ll;
    const int* lenOther   = side ? ll : rl;
    float* cOut           = side ? g_rc : g_lc;

    int wid  = blockIdx.x * (blockDim.x >> 5) + (threadIdx.x >> 5);
    int lane = threadIdx.x & 31;
    int b = wid / LSZ, i = wid % LSZ;
    if (b >= BSZ) return;
    if (i >= lenSelf[b]) return;
    int n = lenOther[b];
    const float* row = attRows + ((size_t)b * LSZ + i) * LSZ;
    const unsigned FULL = 0xffffffffu;

    float v0 = -3.0e38f, v1 = -3.0e38f, v2 = -3.0e38f;
    int i0 = 0x7fffffff, i1 = 0x7fffffff, i2 = 0x7fffffff;
    for (int j = lane; j < n; j += 32) {
        float a = row[j];
        tk_insert(a, j, v0, i0, v1, i1, v2, i2);
    }
#pragma unroll
    for (int off = 16; off >= 1; off >>= 1) {
        float ov0 = __shfl_xor_sync(FULL, v0, off);
        int   oi0 = __shfl_xor_sync(FULL, i0, off);
        float ov1 = __shfl_xor_sync(FULL, v1, off);
        int   oi1 = __shfl_xor_sync(FULL, i1, off);
        float ov2 = __shfl_xor_sync(FULL, v2, off);
        int   oi2 = __shfl_xor_sync(FULL, i2, off);
        tk_insert(ov0, oi0, v0, i0, v1, i1, v2, i2);
        tk_insert(ov1, oi1, v0, i0, v1, i1, v2, i2);
        tk_insert(ov2, oi2, v0, i0, v1, i1, v2, i2);
    }
    float m = v0;

    float S = 0.f, S2 = 0.f;
    for (int j = lane; j < n; j += 32) {
        float e = expf(row[j] - m);
        S += e; S2 += e * e;
    }
#pragma unroll
    for (int off = 16; off >= 1; off >>= 1) {
        S  += __shfl_xor_sync(FULL, S,  off);
        S2 += __shfl_xor_sync(FULL, S2, off);
    }

    float rlenf = (float)n;
    float mean  = 1.0f / rlenf;
    float s2    = S2 / (S * S);
    float w     = (s2 / rlenf - mean * mean) / fmaxf(mean, 0.001f);

    float a0 = 1.0f, a1 = expf(v1 - v0), a2 = expf(v2 - v0);
    float asum = a0 + a1 + a2;
    a0 /= asum; a1 /= asum; a2 /= asum;

    const float* g0 = vecOther + ((size_t)b * LSZ + i0) * DP;
    const float* g1 = vecOther + ((size_t)b * LSZ + i1) * DP;
    const float* g2 = vecOther + ((size_t)b * LSZ + i2) * DP;
    const float* sv = vecSelf  + ((size_t)b * LSZ + i) * DP;
    float* dst      = cOut     + ((size_t)b * LSZ + i) * DP;
    for (int d = lane; d < DP; d += 32) {
        float val = 0.f;
        if (d < DDIM) {
            float ctr = a0 * g0[d] + a1 * g1[d] + a2 * g2[d];
            val = w * fabsf(sv[d] - ctr);
        }
        dst[d] = val;
    }
}

// ---------------- conv GEMM (bf16 split) ----------------
__global__ __launch_bounds__(256) void conv_gemm_kernel(const int* __restrict__ llen,
                                                        const int* __restrict__ rlen) {
    __shared__ unsigned sb[4 * 64 * WP];
    int zb = blockIdx.z;
    int side = zb >> 9, b = zb & 511;
    int m0 = blockIdx.x * 64;
    int n0 = blockIdx.y * 64;
    int len = side ? rlen[b] : llen[b];
    if (m0 >= len) return;

    const float* X = (side ? g_rc : g_lc) + (size_t)b * LSZ * DP;
    float* Zo      = (side ? g_Zr : g_Zl) + (size_t)b * LSZ * NCH;

    int tid  = threadIdx.x;
    int lane = tid & 31;
    int wid  = tid >> 5;
    int wm   = wid & 3, wn = wid >> 2;
    int lrow = tid >> 2;
    int lkq  = (tid & 3) * 8;

    GemmAcc acc;
#pragma unroll
    for (int i = 0; i < 4; i++)
#pragma unroll
        for (int j = 0; j < 4; j++) acc.a[i][j] = 0.f;

    const float* Arow = X + (size_t)(m0 + lrow) * DP;
    const float* Brow = g_wall + (size_t)(n0 + lrow) * DP;
    bool aval = (m0 + lrow) < LSZ;

    for (int k0 = 0; k0 < DP; k0 += 32) {
        gemm_store_phase(sb, Arow, Brow, aval, true, lrow, lkq, k0);
        __syncthreads();
        gemm_math_phase(sb, &acc, wm, wn, lane);
        __syncthreads();
    }

    int r0 = wm * 16 + (lane >> 2);
#pragma unroll
    for (int nf = 0; nf < 4; nf++) {
        int gn = n0 + wn * 32 + nf * 8 + 2 * (lane & 3);
        if (gn < NCH) {
            int gm = m0 + r0;
            if (gm < LSZ)
                *(float2*)(Zo + (size_t)gm * NCH + gn) = make_float2(acc.a[nf][0], acc.a[nf][1]);
            gm += 8;
            if (gm < LSZ)
                *(float2*)(Zo + (size_t)gm * NCH + gn) = make_float2(acc.a[nf][2], acc.a[nf][3]);
        }
    }
}

// ---------------- masked relu-max pooling ----------------
__global__ void combine_kernel(const int* __restrict__ llen, const int* __restrict__ rlen,
                               const float* __restrict__ cb1, const float* __restrict__ cb2,
                               const float* __restrict__ cb3) {
    int b = blockIdx.x, side = blockIdx.y;
    const float* Z = (side ? g_Zr : g_Zl) + (size_t)b * LSZ * NCH;
    int len = side ? rlen[b] : llen[b];
    int j = threadIdx.x;
    if (j >= 300) return;
    float mx = -1e30f;
    if (j < 100) {
        float bias = cb1[j];
        for (int t = 0; t <= len - 1; t++) {
            float s = Z[(size_t)t * NCH + j] + bias;
            mx = fmaxf(mx, fmaxf(s, 0.f));
        }
    } else if (j < 200) {
        int o = j - 100; float bias = cb2[o];
        for (int t = 0; t <= len - 2; t++) {
            float s = Z[(size_t)t * NCH + 100 + o] + Z[(size_t)(t + 1) * NCH + 200 + o] + bias;
            mx = fmaxf(mx, fmaxf(s, 0.f));
        }
    } else {
        int o = j - 200; float bias = cb3[o];
        for (int t = 0; t <= len - 3; t++) {
            float s = Z[(size_t)t * NCH + 300 + o] + Z[(size_t)(t + 1) * NCH + 400 + o]
                    + Z[(size_t)(t + 2) * NCH + 500 + o] + bias;
            mx = fmaxf(mx, fmaxf(s, 0.f));
        }
    }
    g_feats[(size_t)b * NCH + side * 300 + j] = mx;
}

// ---------------- dense head ----------------
__global__ void dense_kernel(const float* __restrict__ dw1, const float* __restrict__ db1,
                             const float* __restrict__ dw2, const float* __restrict__ db2,
                             float* __restrict__ out) {
    int b = blockIdx.x;
    __shared__ float f[NCH];
    __shared__ float h[64];
    int tid = threadIdx.x;
    for (int j = tid; j < NCH; j += blockDim.x) f[j] = g_feats[(size_t)b * NCH + j];
    __syncthreads();
    if (tid < 60) {
        float s = db1[tid];
        for (int j = 0; j < NCH; j++) s += f[j] * dw1[j * 60 + tid];
        h[tid] = fmaxf(s, 0.f);
    }
    __syncthreads();
    if (tid < 2) {
        float s = db2[tid];
        for (int j = 0; j < 60; j++) s += h[j] * dw2[j * 2 + tid];
        out[b * 2 + tid] = s;
    }
}

// ---------------- launch ----------------
extern "C" void kernel_launch(void* const* d_in, const int* in_sizes, int n_in,
                              void* d_out, int out_size) {
    const int*   lt   = (const int*)d_in[0];
    const int*   la   = (const int*)d_in[1];
    const int*   ll   = (const int*)d_in[2];
    const int*   rt   = (const int*)d_in[3];
    const int*   ra   = (const int*)d_in[4];
    const int*   rl   = (const int*)d_in[5];
    const float* wemb = (const float*)d_in[6];
    const float* aemb = (const float*)d_in[7];
    const float* cw1  = (const float*)d_in[8];
    const float* cb1  = (const float*)d_in[9];
    const float* cw2  = (const float*)d_in[10];
    const float* cb2  = (const float*)d_in[11];
    const float* cw3  = (const float*)d_in[12];
    const float* cb3  = (const float*)d_in[13];
    const float* dw1  = (const float*)d_in[14];
    const float* db1  = (const float*)d_in[15];
    const float* dw2  = (const float*)d_in[16];
    const float* db2  = (const float*)d_in[17];
    float* out = (float*)d_out;

    prep_wall_kernel<<<(NPAD * DP + 255) / 256, 256>>>(cw1, cw2, cw3);
    gather_kernel<<<dim3(LSZ, BSZ, 2), 96>>>(lt, la, rt, ra, wemb, aemb);
    att_gemm_kernel<<<dim3(3, 3, BSZ), 256>>>(ll, rl);
    attproc_kernel<<<dim3((BSZ * LSZ) / 4, 2), 128>>>(ll, rl);
    conv_gemm_kernel<<<dim3(3, 10, 2 * BSZ), 256>>>(ll, rl);
    combine_kernel<<<dim3(BSZ, 2), 320>>>(ll, rl, cb1, cb2, cb3);
    dense_kernel<<<BSZ, 128>>>(dw1, db1, dw2, db2, out);
}

// round 5
// speedup vs baseline: 2.8287x; 1.5349x over previous
#include <cuda_runtime.h>
#include <cuda_bf16.h>
#include <math.h>
#include <stdint.h>

// ---------------- problem constants ----------------
#define BSZ   512
#define LSZ   160
#define DDIM  350
#define DP    352     // padded D
#define DPW   176     // DP/2 packed words
#define NCH   600
#define NPAD  640
#define WP    20      // att-gemm smem word pitch
#define CWP   20      // conv-gemm smem word pitch (16 + 4 pad)

// ---------------- device scratch ----------------
__device__ float    g_lvec[(size_t)BSZ * LSZ * DP];
__device__ float    g_rvec[(size_t)BSZ * LSZ * DP];
__device__ float    g_att [(size_t)BSZ * LSZ * LSZ];
__device__ float    g_attT[(size_t)BSZ * LSZ * LSZ];
__device__ unsigned g_lch [(size_t)BSZ * LSZ * DPW];   // l_c split hi (bf16x2)
__device__ unsigned g_lcl [(size_t)BSZ * LSZ * DPW];   // l_c split lo
__device__ unsigned g_rch [(size_t)BSZ * LSZ * DPW];
__device__ unsigned g_rcl [(size_t)BSZ * LSZ * DPW];
__device__ float    g_Zl  [(size_t)BSZ * LSZ * NCH];
__device__ float    g_Zr  [(size_t)BSZ * LSZ * NCH];
__device__ unsigned g_wallh[(size_t)NPAD * DPW];
__device__ unsigned g_walll[(size_t)NPAD * DPW];
__device__ float    g_feats[(size_t)BSZ * NCH];

// ---------------- bf16 split helpers ----------------
__device__ __forceinline__ void split2(float a, float b, unsigned& hi, unsigned& lo) {
    __nv_bfloat162 h = __floats2bfloat162_rn(a, b);
    float ra = a - __bfloat162float(h.x);
    float rb = b - __bfloat162float(h.y);
    __nv_bfloat162 l = __floats2bfloat162_rn(ra, rb);
    hi = *(unsigned*)&h;
    lo = *(unsigned*)&l;
}
__device__ __forceinline__ void mma16(float* c, const unsigned* a, unsigned b0, unsigned b1) {
    asm volatile(
        "mma.sync.aligned.m16n8k16.row.col.f32.bf16.bf16.f32 "
        "{%0,%1,%2,%3}, {%4,%5,%6,%7}, {%8,%9}, {%0,%1,%2,%3};"
        : "+f"(c[0]), "+f"(c[1]), "+f"(c[2]), "+f"(c[3])
        : "r"(a[0]), "r"(a[1]), "r"(a[2]), "r"(a[3]), "r"(b0), "r"(b1));
}
__device__ __forceinline__ void ldx4(unsigned* r, unsigned addr) {
    asm volatile("ldmatrix.sync.aligned.m8n8.x4.shared.b16 {%0,%1,%2,%3}, [%4];"
                 : "=r"(r[0]), "=r"(r[1]), "=r"(r[2]), "=r"(r[3]) : "r"(addr));
}
__device__ __forceinline__ void cp16(unsigned dst, const void* src, bool pred) {
    int sz = pred ? 16 : 0;
    asm volatile("cp.async.ca.shared.global [%0], [%1], 16, %2;"
                 :: "r"(dst), "l"(src), "r"(sz));
}
__device__ __forceinline__ void cpcommit() { asm volatile("cp.async.commit_group;"); }
template<int N> __device__ __forceinline__ void cpwait() {
    asm volatile("cp.async.wait_group %0;" :: "n"(N));
}

// ---------------- build stacked filter matrix (pre-split) ----------------
__global__ void prep_wall_kernel(const float* __restrict__ w1,
                                 const float* __restrict__ w2,
                                 const float* __restrict__ w3) {
    int idx = blockIdx.x * blockDim.x + threadIdx.x;
    if (idx >= NPAD * DPW) return;
    int n = idx / DPW, p = idx % DPW;
    float v[2];
#pragma unroll
    for (int c = 0; c < 2; c++) {
        int k = 2 * p + c;
        float x = 0.f;
        if (k < DDIM && n < NCH) {
            if      (n < 100) x = w1[n * DDIM + k];
            else if (n < 200) x = w2[(n - 100) * (DDIM * 2) + k * 2 + 0];
            else if (n < 300) x = w2[(n - 200) * (DDIM * 2) + k * 2 + 1];
            else if (n < 400) x = w3[(n - 300) * (DDIM * 3) + k * 3 + 0];
            else if (n < 500) x = w3[(n - 400) * (DDIM * 3) + k * 3 + 1];
            else              x = w3[(n - 500) * (DDIM * 3) + k * 3 + 2];
        }
        v[c] = x;
    }
    unsigned hi, lo;
    split2(v[0], v[1], hi, lo);
    g_wallh[idx] = hi;
    g_walll[idx] = lo;
}

// ---------------- embedding gather ----------------
__global__ void gather_kernel(const int* __restrict__ lt, const int* __restrict__ la,
                              const int* __restrict__ rt, const int* __restrict__ ra,
                              const float* __restrict__ wemb, const float* __restrict__ aemb) {
    int l = blockIdx.x, b = blockIdx.y, side = blockIdx.z;
    const int* tok = side ? rt : lt;
    const int* atr = side ? ra : la;
    float* dst = (side ? g_rvec : g_lvec) + ((size_t)(b * LSZ + l)) * DP;
    int t = tok[l * BSZ + b];
    int a = atr[l * BSZ + b];
    const float* wr = wemb + (size_t)t * 300;
    const float* ar = aemb + (size_t)a * 50;
    int q = threadIdx.x;
    if (q < 88) {
        int d0 = q * 4;
        float4 o;
        float* op = (float*)&o;
#pragma unroll
        for (int c = 0; c < 4; c++) {
            int d = d0 + c;
            float v = 0.f;
            if (d < 50) v = __ldg(ar + d);
            else if (d < DDIM) v = __ldg(wr + d - 50);
            op[c] = v;
        }
        *(float4*)(dst + d0) = o;
    }
}

// =====================================================================
// att GEMM (round-4 style, fp32 in, split in registers)
// =====================================================================
#define SM_XH 0
#define SM_XL (64 * WP)
#define SM_WH (2 * 64 * WP)
#define SM_WL (3 * 64 * WP)

struct GemmAcc { float a[4][4]; };

__device__ __forceinline__ void gemm_store_phase(unsigned* sb, const float* Arow, const float* Brow,
                                                 bool aval, bool bval, int lrow, int lkq, int k0) {
#pragma unroll
    for (int h = 0; h < 2; h++) {
        int kk = lkq + h * 4;
        float4 xv = make_float4(0.f, 0.f, 0.f, 0.f);
        float4 wv = make_float4(0.f, 0.f, 0.f, 0.f);
        if (aval) xv = *(const float4*)(Arow + k0 + kk);
        if (bval) wv = *(const float4*)(Brow + k0 + kk);
        unsigned hi, lo;
        int base = lrow * WP + kk / 2;
        split2(xv.x, xv.y, hi, lo); sb[SM_XH + base + 0] = hi; sb[SM_XL + base + 0] = lo;
        split2(xv.z, xv.w, hi, lo); sb[SM_XH + base + 1] = hi; sb[SM_XL + base + 1] = lo;
        split2(wv.x, wv.y, hi, lo); sb[SM_WH + base + 0] = hi; sb[SM_WL + base + 0] = lo;
        split2(wv.z, wv.w, hi, lo); sb[SM_WH + base + 1] = hi; sb[SM_WL + base + 1] = lo;
    }
}

__device__ __forceinline__ void gemm_math_phase(const unsigned* sb, GemmAcc* acc,
                                                int wm, int wn, int lane) {
    int r0 = wm * 16 + (lane >> 2);
    int c  = lane & 3;
#pragma unroll
    for (int ks = 0; ks < 2; ks++) {
        int kw = ks * 8;
        unsigned ah[4], al[4];
        ah[0] = sb[SM_XH + r0 * WP + kw + c];
        ah[1] = sb[SM_XH + (r0 + 8) * WP + kw + c];
        ah[2] = sb[SM_XH + r0 * WP + kw + 4 + c];
        ah[3] = sb[SM_XH + (r0 + 8) * WP + kw + 4 + c];
        al[0] = sb[SM_XL + r0 * WP + kw + c];
        al[1] = sb[SM_XL + (r0 + 8) * WP + kw + c];
        al[2] = sb[SM_XL + r0 * WP + kw + 4 + c];
        al[3] = sb[SM_XL + (r0 + 8) * WP + kw + 4 + c];
#pragma unroll
        for (int nf = 0; nf < 4; nf++) {
            int cn = wn * 32 + nf * 8 + (lane >> 2);
            unsigned bh0 = sb[SM_WH + cn * WP + kw + c];
            unsigned bh1 = sb[SM_WH + cn * WP + kw + 4 + c];
            unsigned bl0 = sb[SM_WL + cn * WP + kw + c];
            unsigned bl1 = sb[SM_WL + cn * WP + kw + 4 + c];
            mma16(acc->a[nf], ah, bh0, bh1);
            mma16(acc->a[nf], ah, bl0, bl1);
            mma16(acc->a[nf], al, bh0, bh1);
        }
    }
}

__global__ __launch_bounds__(256) void att_gemm_kernel(const int* __restrict__ llen,
                                                       const int* __restrict__ rlen) {
    __shared__ unsigned sb[4 * 64 * WP];
    __shared__ float Ts[64 * 68];
    int b  = blockIdx.z;
    int m0 = blockIdx.x * 64;
    int n0 = blockIdx.y * 64;
    if (m0 >= llen[b] || n0 >= rlen[b]) return;

    const float* A  = g_lvec + (size_t)b * LSZ * DP;
    const float* Bv = g_rvec + (size_t)b * LSZ * DP;

    int tid  = threadIdx.x;
    int lane = tid & 31;
    int wid  = tid >> 5;
    int wm   = wid & 3, wn = wid >> 2;
    int lrow = tid >> 2;
    int lkq  = (tid & 3) * 8;

    GemmAcc acc;
#pragma unroll
    for (int i = 0; i < 4; i++)
#pragma unroll
        for (int j = 0; j < 4; j++) acc.a[i][j] = 0.f;

    const float* Arow = A  + (size_t)(m0 + lrow) * DP;
    const float* Brow = Bv + (size_t)(n0 + lrow) * DP;
    bool aval = (m0 + lrow) < LSZ;
    bool bval = (n0 + lrow) < LSZ;

    for (int k0 = 0; k0 < DP; k0 += 32) {
        gemm_store_phase(sb, Arow, Brow, aval, bval, lrow, lkq, k0);
        __syncthreads();
        gemm_math_phase(sb, &acc, wm, wn, lane);
        __syncthreads();
    }

    {
        int r0 = wm * 16 + (lane >> 2);
        int cb = wn * 32 + 2 * (lane & 3);
#pragma unroll
        for (int nf = 0; nf < 4; nf++) {
            int cn = cb + nf * 8;
            Ts[r0 * 68 + cn]           = acc.a[nf][0];
            Ts[r0 * 68 + cn + 1]       = acc.a[nf][1];
            Ts[(r0 + 8) * 68 + cn]     = acc.a[nf][2];
            Ts[(r0 + 8) * 68 + cn + 1] = acc.a[nf][3];
        }
    }
    __syncthreads();

    {
        int row = tid >> 2;
        int gm = m0 + row;
        if (gm < LSZ) {
#pragma unroll
            for (int q = 0; q < 4; q++) {
                int cl = (tid & 3) * 16 + q * 4;
                int gn = n0 + cl;
                if (gn < LSZ)
                    *(float4*)(g_att + ((size_t)b * LSZ + gm) * LSZ + gn) =
                        *(const float4*)&Ts[row * 68 + cl];
            }
        }
    }
    {
        int rr = tid >> 2;
        int gr = n0 + rr;
        if (gr < LSZ) {
#pragma unroll
            for (int q = 0; q < 4; q++) {
                int l0 = (tid & 3) * 16 + q * 4;
                int gl = m0 + l0;
                if (gl < LSZ) {
                    float4 o;
                    o.x = Ts[(l0 + 0) * 68 + rr];
                    o.y = Ts[(l0 + 1) * 68 + rr];
                    o.z = Ts[(l0 + 2) * 68 + rr];
                    o.w = Ts[(l0 + 3) * 68 + rr];
                    *(float4*)(g_attT + ((size_t)b * LSZ + gr) * LSZ + gl) = o;
                }
            }
        }
    }
}

// ---------------- fused softmax / stats / top-3 / counterpart ----------------
__device__ __forceinline__ bool tk_better(float av, int ai, float bv, int bi) {
    return (av > bv) || (av == bv && ai < bi);
}
__device__ __forceinline__ void tk_insert(float nv, int ni,
                                          float& v0, int& i0, float& v1, int& i1, float& v2, int& i2) {
    if (tk_better(nv, ni, v0, i0)) { v2 = v1; i2 = i1; v1 = v0; i1 = i0; v0 = nv; i0 = ni; }
    else if (tk_better(nv, ni, v1, i1)) { v2 = v1; i2 = i1; v1 = nv; i1 = ni; }
    else if (tk_better(nv, ni, v2, i2)) { v2 = nv; i2 = ni; }
}

__global__ void attproc_kernel(const int* __restrict__ ll, const int* __restrict__ rl) {
    int side = blockIdx.y;
    const float* attRows  = side ? g_attT : g_att;
    const float* vecSelf  = side ? g_rvec : g_lvec;
    const float* vecOther = side ? g_lvec : g_rvec;
    const int* lenSelf    = side ? rl : ll;
    const int* lenOther   = side ? ll : rl;
    unsigned* outH        = side ? g_rch : g_lch;
    unsigned* outL        = side ? g_rcl : g_lcl;

    int wid  = blockIdx.x * (blockDim.x >> 5) + (threadIdx.x >> 5);
    int lane = threadIdx.x & 31;
    int b = wid / LSZ, i = wid % LSZ;
    if (b >= BSZ) return;
    if (i >= lenSelf[b]) return;
    int n = lenOther[b];
    const float* row = attRows + ((size_t)b * LSZ + i) * LSZ;
    const unsigned FULL = 0xffffffffu;

    // single-pass row cache in registers
    float rv[5];
#pragma unroll
    for (int k = 0; k < 5; k++) {
        int j = lane + 32 * k;
        rv[k] = (j < n) ? row[j] : -3.0e38f;
    }

    float v0 = -3.0e38f, v1 = -3.0e38f, v2 = -3.0e38f;
    int i0 = 0x7fffffff, i1 = 0x7fffffff, i2 = 0x7fffffff;
#pragma unroll
    for (int k = 0; k < 5; k++) {
        int j = lane + 32 * k;
        if (j < n) tk_insert(rv[k], j, v0, i0, v1, i1, v2, i2);
    }
#pragma unroll
    for (int off = 16; off >= 1; off >>= 1) {
        float ov0 = __shfl_xor_sync(FULL, v0, off);
        int   oi0 = __shfl_xor_sync(FULL, i0, off);
        float ov1 = __shfl_xor_sync(FULL, v1, off);
        int   oi1 = __shfl_xor_sync(FULL, i1, off);
        float ov2 = __shfl_xor_sync(FULL, v2, off);
        int   oi2 = __shfl_xor_sync(FULL, i2, off);
        tk_insert(ov0, oi0, v0, i0, v1, i1, v2, i2);
        tk_insert(ov1, oi1, v0, i0, v1, i1, v2, i2);
        tk_insert(ov2, oi2, v0, i0, v1, i1, v2, i2);
    }
    float m = v0;

    float S = 0.f, S2 = 0.f;
#pragma unroll
    for (int k = 0; k < 5; k++) {
        int j = lane + 32 * k;
        if (j < n) {
            float e = expf(rv[k] - m);
            S += e; S2 += e * e;
        }
    }
#pragma unroll
    for (int off = 16; off >= 1; off >>= 1) {
        S  += __shfl_xor_sync(FULL, S,  off);
        S2 += __shfl_xor_sync(FULL, S2, off);
    }

    float rlenf = (float)n;
    float mean  = 1.0f / rlenf;
    float s2    = S2 / (S * S);
    float w     = (s2 / rlenf - mean * mean) / fmaxf(mean, 0.001f);

    float a0 = 1.0f, a1 = expf(v1 - v0), a2 = expf(v2 - v0);
    float asum = a0 + a1 + a2;
    a0 /= asum; a1 /= asum; a2 /= asum;

    const float* g0 = vecOther + ((size_t)b * LSZ + i0) * DP;
    const float* g1 = vecOther + ((size_t)b * LSZ + i1) * DP;
    const float* g2 = vecOther + ((size_t)b * LSZ + i2) * DP;
    const float* sv = vecSelf  + ((size_t)b * LSZ + i) * DP;
    size_t rw       = ((size_t)b * LSZ + i) * DPW;

#pragma unroll
    for (int k = 0; k < 6; k++) {
        int p = lane + 32 * k;
        if (p < DPW) {
            float x0 = 0.f, x1 = 0.f;
            int d = 2 * p;
            if (d < DDIM) {
                float ctr = a0 * g0[d] + a1 * g1[d] + a2 * g2[d];
                x0 = w * fabsf(sv[d] - ctr);
            }
            if (d + 1 < DDIM) {
                float ctr = a0 * g0[d + 1] + a1 * g1[d + 1] + a2 * g2[d + 1];
                x1 = w * fabsf(sv[d + 1] - ctr);
            }
            unsigned hi, lo;
            split2(x0, x1, hi, lo);
            outH[rw + p] = hi;
            outL[rw + p] = lo;
        }
    }
}

// =====================================================================
// conv GEMM: 64(m) x 128(n) block, 8 warps of 32x32, cp.async 2-stage,
// ldmatrix fragment loads, pre-split bf16 hi/lo operands.
// stage layout (words): Ah[64*CWP] | Al[64*CWP] | Bh[128*CWP] | Bl[128*CWP]
// =====================================================================
#define STG_W  (64 * CWP + 64 * CWP + 128 * CWP + 128 * CWP)   // 7680 words
#define OFF_AH 0
#define OFF_AL (64 * CWP)
#define OFF_BH (2 * 64 * CWP)
#define OFF_BL (2 * 64 * CWP + 128 * CWP)
#define NKB    11

__global__ __launch_bounds__(256) void conv_gemm_kernel(const int* __restrict__ llen,
                                                        const int* __restrict__ rlen) {
    extern __shared__ unsigned smw[];
    int zb = blockIdx.z;
    int side = zb >> 9, b = zb & 511;
    int m0 = blockIdx.x * 64;
    int n0 = blockIdx.y * 128;
    int len = side ? rlen[b] : llen[b];
    if (m0 >= len) return;

    const unsigned* Ah = (side ? g_rch : g_lch) + (size_t)b * LSZ * DPW;
    const unsigned* Al = (side ? g_rcl : g_lcl) + (size_t)b * LSZ * DPW;
    float* Zo = (side ? g_Zr : g_Zl) + (size_t)b * LSZ * NCH;

    int tid  = threadIdx.x;
    int lane = tid & 31;
    int wid  = tid >> 5;
    int wm   = wid & 1;       // m: 2 groups of 32
    int wn   = wid >> 1;      // n: 4 groups of 32

    unsigned sbase = (unsigned)__cvta_generic_to_shared(smw);

    // copy indices
    int ar = tid >> 2, ac = tid & 3;                 // A: one chunk per thread
    int agm = m0 + ar;
    bool aok = agm < LSZ;
    const unsigned* asrcH = Ah + (size_t)(aok ? agm : 0) * DPW + ac * 4;
    const unsigned* asrcL = Al + (size_t)(aok ? agm : 0) * DPW + ac * 4;
    unsigned adstH = (OFF_AH + ar * CWP + ac * 4);
    unsigned adstL = (OFF_AL + ar * CWP + ac * 4);

    float acc[2][4][4];
#pragma unroll
    for (int ms = 0; ms < 2; ms++)
#pragma unroll
        for (int nf = 0; nf < 4; nf++)
#pragma unroll
            for (int q = 0; q < 4; q++) acc[ms][nf][q] = 0.f;

#define COPY_STAGE(kb, s) do {                                                    \
    unsigned sb0 = sbase + (s) * (STG_W * 4);                                     \
    cp16(sb0 + adstH * 4, asrcH + (kb) * 16, aok);                                \
    cp16(sb0 + adstL * 4, asrcL + (kb) * 16, aok);                                \
    _Pragma("unroll")                                                             \
    for (int q = 0; q < 2; q++) {                                                 \
        int cid = tid + 256 * q;                                                  \
        int br = cid >> 2, bc = cid & 3;                                          \
        cp16(sb0 + (OFF_BH + br * CWP + bc * 4) * 4,                              \
             g_wallh + (size_t)(n0 + br) * DPW + (kb) * 16 + bc * 4, true);       \
        cp16(sb0 + (OFF_BL + br * CWP + bc * 4) * 4,                              \
             g_walll + (size_t)(n0 + br) * DPW + (kb) * 16 + bc * 4, true);       \
    }                                                                             \
} while (0)

    COPY_STAGE(0, 0);
    cpcommit();

    for (int kb = 0; kb < NKB; kb++) {
        if (kb + 1 < NKB) {
            COPY_STAGE(kb + 1, (kb + 1) & 1);
            cpcommit();
            cpwait<1>();
        } else {
            cpwait<0>();
        }
        __syncthreads();

        unsigned sb0 = sbase + (kb & 1) * (STG_W * 4);
#pragma unroll
        for (int ks = 0; ks < 2; ks++) {
            // A fragments (hi & lo) for 2 m-steps
            unsigned ahf[2][4], alf[2][4];
#pragma unroll
            for (int ms = 0; ms < 2; ms++) {
                int r = wm * 32 + ms * 16 + (lane & 7) + ((lane >> 3) & 1) * 8;
                int c = ks * 2 + (lane >> 4);
                ldx4(ahf[ms], sb0 + (OFF_AH + r * CWP + c * 4) * 4);
                ldx4(alf[ms], sb0 + (OFF_AL + r * CWP + c * 4) * 4);
            }
            // B fragments: nf pairs
#pragma unroll
            for (int nfp = 0; nfp < 2; nfp++) {
                int rB = wn * 32 + nfp * 16 + ((lane >> 4) & 1) * 8 + (lane & 7);
                int cB = ks * 2 + ((lane >> 3) & 1);
                unsigned bh[4], bl[4];
                ldx4(bh, sb0 + (OFF_BH + rB * CWP + cB * 4) * 4);
                ldx4(bl, sb0 + (OFF_BL + rB * CWP + cB * 4) * 4);
#pragma unroll
                for (int ms = 0; ms < 2; ms++) {
                    mma16(acc[ms][2 * nfp],     ahf[ms], bh[0], bh[1]);
                    mma16(acc[ms][2 * nfp],     ahf[ms], bl[0], bl[1]);
                    mma16(acc[ms][2 * nfp],     alf[ms], bh[0], bh[1]);
                    mma16(acc[ms][2 * nfp + 1], ahf[ms], bh[2], bh[3]);
                    mma16(acc[ms][2 * nfp + 1], ahf[ms], bl[2], bl[3]);
                    mma16(acc[ms][2 * nfp + 1], alf[ms], bh[2], bh[3]);
                }
            }
        }
        __syncthreads();
    }
#undef COPY_STAGE

    // epilogue: direct float2 stores
#pragma unroll
    for (int ms = 0; ms < 2; ms++) {
        int rbase = m0 + wm * 32 + ms * 16 + (lane >> 2);
#pragma unroll
        for (int nf = 0; nf < 4; nf++) {
            int gn = n0 + wn * 32 + nf * 8 + 2 * (lane & 3);
            if (gn < NCH) {
                if (rbase < LSZ)
                    *(float2*)(Zo + (size_t)rbase * NCH + gn) =
                        make_float2(acc[ms][nf][0], acc[ms][nf][1]);
                if (rbase + 8 < LSZ)
                    *(float2*)(Zo + (size_t)(rbase + 8) * NCH + gn) =
                        make_float2(acc[ms][nf][2], acc[ms][nf][3]);
            }
        }
    }
}

// ---------------- masked relu-max pooling ----------------
__global__ void combine_kernel(const int* __restrict__ llen, const int* __restrict__ rlen,
                               const float* __restrict__ cb1, const float* __restrict__ cb2,
                               const float* __restrict__ cb3) {
    int b = blockIdx.x, side = blockIdx.y;
    const float* Z = (side ? g_Zr : g_Zl) + (size_t)b * LSZ * NCH;
    int len = side ? rlen[b] : llen[b];
    int j = threadIdx.x;
    if (j >= 300) return;
    float mx = -1e30f;
    if (j < 100) {
        float bias = cb1[j];
        for (int t = 0; t <= len - 1; t++) {
            float s = Z[(size_t)t * NCH + j] + bias;
            mx = fmaxf(mx, fmaxf(s, 0.f));
        }
    } else if (j < 200) {
        int o = j - 100; float bias = cb2[o];
        for (int t = 0; t <= len - 2; t++) {
            float s = Z[(size_t)t * NCH + 100 + o] + Z[(size_t)(t + 1) * NCH + 200 + o] + bias;
            mx = fmaxf(mx, fmaxf(s, 0.f));
        }
    } else {
        int o = j - 200; float bias = cb3[o];
        for (int t = 0; t <= len - 3; t++) {
            float s = Z[(size_t)t * NCH + 300 + o] + Z[(size_t)(t + 1) * NCH + 400 + o]
                    + Z[(size_t)(t + 2) * NCH + 500 + o] + bias;
            mx = fmaxf(mx, fmaxf(s, 0.f));
        }
    }
    g_feats[(size_t)b * NCH + side * 300 + j] = mx;
}

// ---------------- dense head ----------------
__global__ void dense_kernel(const float* __restrict__ dw1, const float* __restrict__ db1,
                             const float* __restrict__ dw2, const float* __restrict__ db2,
                             float* __restrict__ out) {
    int b = blockIdx.x;
    __shared__ float f[NCH];
    __shared__ float h[64];
    int tid = threadIdx.x;
    for (int j = tid; j < NCH; j += blockDim.x) f[j] = g_feats[(size_t)b * NCH + j];
    __syncthreads();
    if (tid < 60) {
        float s = db1[tid];
        for (int j = 0; j < NCH; j++) s += f[j] * dw1[j * 60 + tid];
        h[tid] = fmaxf(s, 0.f);
    }
    __syncthreads();
    if (tid < 2) {
        float s = db2[tid];
        for (int j = 0; j < 60; j++) s += h[j] * dw2[j * 2 + tid];
        out[b * 2 + tid] = s;
    }
}

// ---------------- launch ----------------
extern "C" void kernel_launch(void* const* d_in, const int* in_sizes, int n_in,
                              void* d_out, int out_size) {
    const int*   lt   = (const int*)d_in[0];
    const int*   la   = (const int*)d_in[1];
    const int*   ll   = (const int*)d_in[2];
    const int*   rt   = (const int*)d_in[3];
    const int*   ra   = (const int*)d_in[4];
    const int*   rl   = (const int*)d_in[5];
    const float* wemb = (const float*)d_in[6];
    const float* aemb = (const float*)d_in[7];
    const float* cw1  = (const float*)d_in[8];
    const float* cb1  = (const float*)d_in[9];
    const float* cw2  = (const float*)d_in[10];
    const float* cb2  = (const float*)d_in[11];
    const float* cw3  = (const float*)d_in[12];
    const float* cb3  = (const float*)d_in[13];
    const float* dw1  = (const float*)d_in[14];
    const float* db1  = (const float*)d_in[15];
    const float* dw2  = (const float*)d_in[16];
    const float* db2  = (const float*)d_in[17];
    float* out = (float*)d_out;

    const int convSmem = STG_W * 4 * 2;   // 61440 bytes
    cudaFuncSetAttribute(conv_gemm_kernel,
                         cudaFuncAttributeMaxDynamicSharedMemorySize, convSmem);

    prep_wall_kernel<<<(NPAD * DPW + 255) / 256, 256>>>(cw1, cw2, cw3);
    gather_kernel<<<dim3(LSZ, BSZ, 2), 96>>>(lt, la, rt, ra, wemb, aemb);
    att_gemm_kernel<<<dim3(3, 3, BSZ), 256>>>(ll, rl);
    attproc_kernel<<<dim3((BSZ * LSZ) / 4, 2), 128>>>(ll, rl);
    conv_gemm_kernel<<<dim3(3, 5, 2 * BSZ), 256, convSmem>>>(ll, rl);
    combine_kernel<<<dim3(BSZ, 2), 320>>>(ll, rl, cb1, cb2, cb3);
    dense_kernel<<<BSZ, 128>>>(dw1, db1, dw2, db2, out);
}

// round 6
// speedup vs baseline: 2.9710x; 1.0503x over previous
#include <cuda_runtime.h>
#include <cuda_bf16.h>
#include <math.h>
#include <stdint.h>

// ---------------- problem constants ----------------
#define BSZ   512
#define LSZ   160
#define DDIM  350
#define DP    352     // padded D
#define DPW   176     // DP/2 packed words
#define NCH   600
#define NPAD  640
#define WP    20      // att-gemm smem word pitch
#define CWP   20      // conv-gemm smem word pitch (16 + 4 pad)
#define ZPITCH 132    // pooled Z smem pitch

// ---------------- device scratch ----------------
__device__ float    g_lvec[(size_t)BSZ * LSZ * DP];
__device__ float    g_rvec[(size_t)BSZ * LSZ * DP];
__device__ float    g_att [(size_t)BSZ * LSZ * LSZ];
__device__ float    g_attT[(size_t)BSZ * LSZ * LSZ];
__device__ unsigned g_lch [(size_t)BSZ * LSZ * DPW];   // l_c split hi (bf16x2)
__device__ unsigned g_lcl [(size_t)BSZ * LSZ * DPW];   // l_c split lo
__device__ unsigned g_rch [(size_t)BSZ * LSZ * DPW];
__device__ unsigned g_rcl [(size_t)BSZ * LSZ * DPW];
__device__ unsigned g_wallh[(size_t)NPAD * DPW];       // permuted channel layout
__device__ unsigned g_walll[(size_t)NPAD * DPW];
__device__ float    g_feats[(size_t)BSZ * NCH];

// ---------------- bf16 split helpers ----------------
__device__ __forceinline__ void split2(float a, float b, unsigned& hi, unsigned& lo) {
    __nv_bfloat162 h = __floats2bfloat162_rn(a, b);
    float ra = a - __bfloat162float(h.x);
    float rb = b - __bfloat162float(h.y);
    __nv_bfloat162 l = __floats2bfloat162_rn(ra, rb);
    hi = *(unsigned*)&h;
    lo = *(unsigned*)&l;
}
__device__ __forceinline__ void mma16(float* c, const unsigned* a, unsigned b0, unsigned b1) {
    asm volatile(
        "mma.sync.aligned.m16n8k16.row.col.f32.bf16.bf16.f32 "
        "{%0,%1,%2,%3}, {%4,%5,%6,%7}, {%8,%9}, {%0,%1,%2,%3};"
        : "+f"(c[0]), "+f"(c[1]), "+f"(c[2]), "+f"(c[3])
        : "r"(a[0]), "r"(a[1]), "r"(a[2]), "r"(a[3]), "r"(b0), "r"(b1));
}
__device__ __forceinline__ void ldx4(unsigned* r, unsigned addr) {
    asm volatile("ldmatrix.sync.aligned.m8n8.x4.shared.b16 {%0,%1,%2,%3}, [%4];"
                 : "=r"(r[0]), "=r"(r[1]), "=r"(r[2]), "=r"(r[3]) : "r"(addr));
}
__device__ __forceinline__ void cp16(unsigned dst, const void* src, bool pred) {
    int sz = pred ? 16 : 0;
    asm volatile("cp.async.ca.shared.global [%0], [%1], 16, %2;"
                 :: "r"(dst), "l"(src), "r"(sz));
}
__device__ __forceinline__ void cpcommit() { asm volatile("cp.async.commit_group;"); }
template<int N> __device__ __forceinline__ void cpwait() {
    asm volatile("cp.async.wait_group %0;" :: "n"(N));
}

// ---------------- zero feats ----------------
__global__ void feats_init_kernel() {
    int i = blockIdx.x * blockDim.x + threadIdx.x;
    if (i < BSZ * NCH) g_feats[i] = 0.f;
}

// ---------------- build stacked filter matrix (permuted + pre-split) -----------
// permuted channel nn: tile = nn/128, j = nn%128; j<120: o = tile*20 + j/6, g = j%6
//   g=0: conv1[o];  g=1,2: conv2[o] tap g-1;  g=3..5: conv3[o] tap g-3
__global__ void prep_wall_kernel(const float* __restrict__ w1,
                                 const float* __restrict__ w2,
                                 const float* __restrict__ w3) {
    int idx = blockIdx.x * blockDim.x + threadIdx.x;
    if (idx >= NPAD * DPW) return;
    int nn = idx / DPW, p = idx % DPW;
    int tile = nn >> 7, j = nn & 127;
    int o = tile * 20 + j / 6;
    int g = j % 6;
    bool valid = (j < 120) && (o < 100);
    float v[2];
#pragma unroll
    for (int c = 0; c < 2; c++) {
        int k = 2 * p + c;
        float x = 0.f;
        if (valid && k < DDIM) {
            if      (g == 0) x = w1[o * DDIM + k];
            else if (g <= 2) x = w2[o * (DDIM * 2) + k * 2 + (g - 1)];
            else             x = w3[o * (DDIM * 3) + k * 3 + (g - 3)];
        }
        v[c] = x;
    }
    unsigned hi, lo;
    split2(v[0], v[1], hi, lo);
    g_wallh[idx] = hi;
    g_walll[idx] = lo;
}

// ---------------- embedding gather ----------------
__global__ void gather_kernel(const int* __restrict__ lt, const int* __restrict__ la,
                              const int* __restrict__ rt, const int* __restrict__ ra,
                              const float* __restrict__ wemb, const float* __restrict__ aemb) {
    int l = blockIdx.x, b = blockIdx.y, side = blockIdx.z;
    const int* tok = side ? rt : lt;
    const int* atr = side ? ra : la;
    float* dst = (side ? g_rvec : g_lvec) + ((size_t)(b * LSZ + l)) * DP;
    int t = tok[l * BSZ + b];
    int a = atr[l * BSZ + b];
    const float* wr = wemb + (size_t)t * 300;
    const float* ar = aemb + (size_t)a * 50;
    int q = threadIdx.x;
    if (q < 88) {
        int d0 = q * 4;
        float4 o;
        float* op = (float*)&o;
#pragma unroll
        for (int c = 0; c < 4; c++) {
            int d = d0 + c;
            float v = 0.f;
            if (d < 50) v = __ldg(ar + d);
            else if (d < DDIM) v = __ldg(wr + d - 50);
            op[c] = v;
        }
        *(float4*)(dst + d0) = o;
    }
}

// =====================================================================
// att GEMM (fp32 in, split in registers)
// =====================================================================
#define SM_XH 0
#define SM_XL (64 * WP)
#define SM_WH (2 * 64 * WP)
#define SM_WL (3 * 64 * WP)

struct GemmAcc { float a[4][4]; };

__device__ __forceinline__ void gemm_store_phase(unsigned* sb, const float* Arow, const float* Brow,
                                                 bool aval, bool bval, int lrow, int lkq, int k0) {
#pragma unroll
    for (int h = 0; h < 2; h++) {
        int kk = lkq + h * 4;
        float4 xv = make_float4(0.f, 0.f, 0.f, 0.f);
        float4 wv = make_float4(0.f, 0.f, 0.f, 0.f);
        if (aval) xv = *(const float4*)(Arow + k0 + kk);
        if (bval) wv = *(const float4*)(Brow + k0 + kk);
        unsigned hi, lo;
        int base = lrow * WP + kk / 2;
        split2(xv.x, xv.y, hi, lo); sb[SM_XH + base + 0] = hi; sb[SM_XL + base + 0] = lo;
        split2(xv.z, xv.w, hi, lo); sb[SM_XH + base + 1] = hi; sb[SM_XL + base + 1] = lo;
        split2(wv.x, wv.y, hi, lo); sb[SM_WH + base + 0] = hi; sb[SM_WL + base + 0] = lo;
        split2(wv.z, wv.w, hi, lo); sb[SM_WH + base + 1] = hi; sb[SM_WL + base + 1] = lo;
    }
}

__device__ __forceinline__ void gemm_math_phase(const unsigned* sb, GemmAcc* acc,
                                                int wm, int wn, int lane) {
    int r0 = wm * 16 + (lane >> 2);
    int c  = lane & 3;
#pragma unroll
    for (int ks = 0; ks < 2; ks++) {
        int kw = ks * 8;
        unsigned ah[4], al[4];
        ah[0] = sb[SM_XH + r0 * WP + kw + c];
        ah[1] = sb[SM_XH + (r0 + 8) * WP + kw + c];
        ah[2] = sb[SM_XH + r0 * WP + kw + 4 + c];
        ah[3] = sb[SM_XH + (r0 + 8) * WP + kw + 4 + c];
        al[0] = sb[SM_XL + r0 * WP + kw + c];
        al[1] = sb[SM_XL + (r0 + 8) * WP + kw + c];
        al[2] = sb[SM_XL + r0 * WP + kw + 4 + c];
        al[3] = sb[SM_XL + (r0 + 8) * WP + kw + 4 + c];
#pragma unroll
        for (int nf = 0; nf < 4; nf++) {
            int cn = wn * 32 + nf * 8 + (lane >> 2);
            unsigned bh0 = sb[SM_WH + cn * WP + kw + c];
            unsigned bh1 = sb[SM_WH + cn * WP + kw + 4 + c];
            unsigned bl0 = sb[SM_WL + cn * WP + kw + c];
            unsigned bl1 = sb[SM_WL + cn * WP + kw + 4 + c];
            mma16(acc->a[nf], ah, bh0, bh1);
            mma16(acc->a[nf], ah, bl0, bl1);
            mma16(acc->a[nf], al, bh0, bh1);
        }
    }
}

__global__ __launch_bounds__(256) void att_gemm_kernel(const int* __restrict__ llen,
                                                       const int* __restrict__ rlen) {
    __shared__ unsigned sb[4 * 64 * WP];
    __shared__ float Ts[64 * 68];
    int b  = blockIdx.z;
    int m0 = blockIdx.x * 64;
    int n0 = blockIdx.y * 64;
    if (m0 >= llen[b] || n0 >= rlen[b]) return;

    const float* A  = g_lvec + (size_t)b * LSZ * DP;
    const float* Bv = g_rvec + (size_t)b * LSZ * DP;

    int tid  = threadIdx.x;
    int lane = tid & 31;
    int wid  = tid >> 5;
    int wm   = wid & 3, wn = wid >> 2;
    int lrow = tid >> 2;
    int lkq  = (tid & 3) * 8;

    GemmAcc acc;
#pragma unroll
    for (int i = 0; i < 4; i++)
#pragma unroll
        for (int j = 0; j < 4; j++) acc.a[i][j] = 0.f;

    const float* Arow = A  + (size_t)(m0 + lrow) * DP;
    const float* Brow = Bv + (size_t)(n0 + lrow) * DP;
    bool aval = (m0 + lrow) < LSZ;
    bool bval = (n0 + lrow) < LSZ;

    for (int k0 = 0; k0 < DP; k0 += 32) {
        gemm_store_phase(sb, Arow, Brow, aval, bval, lrow, lkq, k0);
        __syncthreads();
        gemm_math_phase(sb, &acc, wm, wn, lane);
        __syncthreads();
    }

    {
        int r0 = wm * 16 + (lane >> 2);
        int cb = wn * 32 + 2 * (lane & 3);
#pragma unroll
        for (int nf = 0; nf < 4; nf++) {
            int cn = cb + nf * 8;
            Ts[r0 * 68 + cn]           = acc.a[nf][0];
            Ts[r0 * 68 + cn + 1]       = acc.a[nf][1];
            Ts[(r0 + 8) * 68 + cn]     = acc.a[nf][2];
            Ts[(r0 + 8) * 68 + cn + 1] = acc.a[nf][3];
        }
    }
    __syncthreads();

    {
        int row = tid >> 2;
        int gm = m0 + row;
        if (gm < LSZ) {
#pragma unroll
            for (int q = 0; q < 4; q++) {
                int cl = (tid & 3) * 16 + q * 4;
                int gn = n0 + cl;
                if (gn < LSZ)
                    *(float4*)(g_att + ((size_t)b * LSZ + gm) * LSZ + gn) =
                        *(const float4*)&Ts[row * 68 + cl];
            }
        }
    }
    {
        int rr = tid >> 2;
        int gr = n0 + rr;
        if (gr < LSZ) {
#pragma unroll
            for (int q = 0; q < 4; q++) {
                int l0 = (tid & 3) * 16 + q * 4;
                int gl = m0 + l0;
                if (gl < LSZ) {
                    float4 o;
                    o.x = Ts[(l0 + 0) * 68 + rr];
                    o.y = Ts[(l0 + 1) * 68 + rr];
                    o.z = Ts[(l0 + 2) * 68 + rr];
                    o.w = Ts[(l0 + 3) * 68 + rr];
                    *(float4*)(g_attT + ((size_t)b * LSZ + gr) * LSZ + gl) = o;
                }
            }
        }
    }
}

// ---------------- fused softmax / stats / top-3 / counterpart ----------------
__device__ __forceinline__ bool tk_better(float av, int ai, float bv, int bi) {
    return (av > bv) || (av == bv && ai < bi);
}
__device__ __forceinline__ void tk_insert(float nv, int ni,
                                          float& v0, int& i0, float& v1, int& i1, float& v2, int& i2) {
    if (tk_better(nv, ni, v0, i0)) { v2 = v1; i2 = i1; v1 = v0; i1 = i0; v0 = nv; i0 = ni; }
    else if (tk_better(nv, ni, v1, i1)) { v2 = v1; i2 = i1; v1 = nv; i1 = ni; }
    else if (tk_better(nv, ni, v2, i2)) { v2 = nv; i2 = ni; }
}

__global__ void attproc_kernel(const int* __restrict__ ll, const int* __restrict__ rl) {
    int side = blockIdx.y;
    const float* attRows  = side ? g_attT : g_att;
    const float* vecSelf  = side ? g_rvec : g_lvec;
    const float* vecOther = side ? g_lvec : g_rvec;
    const int* lenSelf    = side ? rl : ll;
    const int* lenOther   = side ? ll : rl;
    unsigned* outH        = side ? g_rch : g_lch;
    unsigned* outL        = side ? g_rcl : g_lcl;

    int wid  = blockIdx.x * (blockDim.x >> 5) + (threadIdx.x >> 5);
    int lane = threadIdx.x & 31;
    int b = wid / LSZ, i = wid % LSZ;
    if (b >= BSZ) return;
    if (i >= lenSelf[b]) return;
    int n = lenOther[b];
    const float* row = attRows + ((size_t)b * LSZ + i) * LSZ;
    const unsigned FULL = 0xffffffffu;

    float rv[5];
#pragma unroll
    for (int k = 0; k < 5; k++) {
        int j = lane + 32 * k;
        rv[k] = (j < n) ? row[j] : -3.0e38f;
    }

    float v0 = -3.0e38f, v1 = -3.0e38f, v2 = -3.0e38f;
    int i0 = 0x7fffffff, i1 = 0x7fffffff, i2 = 0x7fffffff;
#pragma unroll
    for (int k = 0; k < 5; k++) {
        int j = lane + 32 * k;
        if (j < n) tk_insert(rv[k], j, v0, i0, v1, i1, v2, i2);
    }
#pragma unroll
    for (int off = 16; off >= 1; off >>= 1) {
        float ov0 = __shfl_xor_sync(FULL, v0, off);
        int   oi0 = __shfl_xor_sync(FULL, i0, off);
        float ov1 = __shfl_xor_sync(FULL, v1, off);
        int   oi1 = __shfl_xor_sync(FULL, i1, off);
        float ov2 = __shfl_xor_sync(FULL, v2, off);
        int   oi2 = __shfl_xor_sync(FULL, i2, off);
        tk_insert(ov0, oi0, v0, i0, v1, i1, v2, i2);
        tk_insert(ov1, oi1, v0, i0, v1, i1, v2, i2);
        tk_insert(ov2, oi2, v0, i0, v1, i1, v2, i2);
    }
    float m = v0;

    float S = 0.f, S2 = 0.f;
#pragma unroll
    for (int k = 0; k < 5; k++) {
        int j = lane + 32 * k;
        if (j < n) {
            float e = expf(rv[k] - m);
            S += e; S2 += e * e;
        }
    }
#pragma unroll
    for (int off = 16; off >= 1; off >>= 1) {
        S  += __shfl_xor_sync(FULL, S,  off);
        S2 += __shfl_xor_sync(FULL, S2, off);
    }

    float rlenf = (float)n;
    float mean  = 1.0f / rlenf;
    float s2    = S2 / (S * S);
    float w     = (s2 / rlenf - mean * mean) / fmaxf(mean, 0.001f);

    float a0 = 1.0f, a1 = expf(v1 - v0), a2 = expf(v2 - v0);
    float asum = a0 + a1 + a2;
    a0 /= asum; a1 /= asum; a2 /= asum;

    const float2* G0 = (const float2*)(vecOther + ((size_t)b * LSZ + i0) * DP);
    const float2* G1 = (const float2*)(vecOther + ((size_t)b * LSZ + i1) * DP);
    const float2* G2 = (const float2*)(vecOther + ((size_t)b * LSZ + i2) * DP);
    const float2* SV = (const float2*)(vecSelf  + ((size_t)b * LSZ + i) * DP);
    size_t rw        = ((size_t)b * LSZ + i) * DPW;

#pragma unroll
    for (int k = 0; k < 6; k++) {
        int p = lane + 32 * k;
        if (p < DPW) {
            float x0 = 0.f, x1 = 0.f;
            if (p < 175) {       // d = 2p, 2p+1 < 350
                float2 e0 = G0[p], e1 = G1[p], e2 = G2[p], s = SV[p];
                float c0 = a0 * e0.x + a1 * e1.x + a2 * e2.x;
                float c1 = a0 * e0.y + a1 * e1.y + a2 * e2.y;
                x0 = w * fabsf(s.x - c0);
                x1 = w * fabsf(s.y - c1);
            }
            unsigned hi, lo;
            split2(x0, x1, hi, lo);
            outH[rw + p] = hi;
            outL[rw + p] = lo;
        }
    }
}

// =====================================================================
// conv GEMM fused with relu-max pooling.
// 64(m, stride-62 overlapped) x 128(n = 20 o-groups of 6 ch + 8 pad),
// cp.async 2-stage, ldmatrix, pre-split operands. Epilogue: acc -> smem
// Z-tile (aliased over stage buffers) -> per-(o,conv) pooling -> atomicMax.
// =====================================================================
#define STG_W  (64 * CWP + 64 * CWP + 128 * CWP + 128 * CWP)   // 7680 words
#define OFF_AH 0
#define OFF_AL (64 * CWP)
#define OFF_BH (2 * 64 * CWP)
#define OFF_BL (2 * 64 * CWP + 128 * CWP)
#define NKB    11

__global__ __launch_bounds__(256) void conv_gemm_kernel(const int* __restrict__ llen,
                                                        const int* __restrict__ rlen,
                                                        const float* __restrict__ cb1,
                                                        const float* __restrict__ cb2,
                                                        const float* __restrict__ cb3) {
    extern __shared__ unsigned smw[];
    int zb = blockIdx.z;
    int side = zb >> 9, b = zb & 511;
    int m0 = blockIdx.x * 62;          // overlapped m-tiles: 0, 62, 124
    int tileN = blockIdx.y;            // 0..4, channels tileN*128..+127
    int len = side ? rlen[b] : llen[b];
    if (m0 >= len) return;

    const unsigned* Ah = (side ? g_rch : g_lch) + (size_t)b * LSZ * DPW;
    const unsigned* Al = (side ? g_rcl : g_lcl) + (size_t)b * LSZ * DPW;
    int n0 = tileN * 128;

    int tid  = threadIdx.x;
    int lane = tid & 31;
    int wid  = tid >> 5;
    int wm   = wid & 1;
    int wn   = wid >> 1;

    unsigned sbase = (unsigned)__cvta_generic_to_shared(smw);

    int ar = tid >> 2, ac = tid & 3;
    int agm = m0 + ar;
    bool aok = agm < LSZ;
    const unsigned* asrcH = Ah + (size_t)(aok ? agm : 0) * DPW + ac * 4;
    const unsigned* asrcL = Al + (size_t)(aok ? agm : 0) * DPW + ac * 4;
    unsigned adstH = (OFF_AH + ar * CWP + ac * 4);
    unsigned adstL = (OFF_AL + ar * CWP + ac * 4);

    float acc[2][4][4];
#pragma unroll
    for (int ms = 0; ms < 2; ms++)
#pragma unroll
        for (int nf = 0; nf < 4; nf++)
#pragma unroll
            for (int q = 0; q < 4; q++) acc[ms][nf][q] = 0.f;

#define COPY_STAGE(kb, s) do {                                                    \
    unsigned sb0 = sbase + (s) * (STG_W * 4);                                     \
    cp16(sb0 + adstH * 4, asrcH + (kb) * 16, aok);                                \
    cp16(sb0 + adstL * 4, asrcL + (kb) * 16, aok);                                \
    _Pragma("unroll")                                                             \
    for (int q = 0; q < 2; q++) {                                                 \
        int cid = tid + 256 * q;                                                  \
        int br = cid >> 2, bc = cid & 3;                                          \
        cp16(sb0 + (OFF_BH + br * CWP + bc * 4) * 4,                              \
             g_wallh + (size_t)(n0 + br) * DPW + (kb) * 16 + bc * 4, true);       \
        cp16(sb0 + (OFF_BL + br * CWP + bc * 4) * 4,                              \
             g_walll + (size_t)(n0 + br) * DPW + (kb) * 16 + bc * 4, true);       \
    }                                                                             \
} while (0)

    COPY_STAGE(0, 0);
    cpcommit();

    for (int kb = 0; kb < NKB; kb++) {
        if (kb + 1 < NKB) {
            COPY_STAGE(kb + 1, (kb + 1) & 1);
            cpcommit();
            cpwait<1>();
        } else {
            cpwait<0>();
        }
        __syncthreads();

        unsigned sb0 = sbase + (kb & 1) * (STG_W * 4);
#pragma unroll
        for (int ks = 0; ks < 2; ks++) {
            unsigned ahf[2][4], alf[2][4];
#pragma unroll
            for (int ms = 0; ms < 2; ms++) {
                int r = wm * 32 + ms * 16 + (lane & 7) + ((lane >> 3) & 1) * 8;
                int c = ks * 2 + (lane >> 4);
                ldx4(ahf[ms], sb0 + (OFF_AH + r * CWP + c * 4) * 4);
                ldx4(alf[ms], sb0 + (OFF_AL + r * CWP + c * 4) * 4);
            }
#pragma unroll
            for (int nfp = 0; nfp < 2; nfp++) {
                int rB = wn * 32 + nfp * 16 + ((lane >> 4) & 1) * 8 + (lane & 7);
                int cB = ks * 2 + ((lane >> 3) & 1);
                unsigned bh[4], bl[4];
                ldx4(bh, sb0 + (OFF_BH + rB * CWP + cB * 4) * 4);
                ldx4(bl, sb0 + (OFF_BL + rB * CWP + cB * 4) * 4);
#pragma unroll
                for (int ms = 0; ms < 2; ms++) {
                    mma16(acc[ms][2 * nfp],     ahf[ms], bh[0], bh[1]);
                    mma16(acc[ms][2 * nfp],     ahf[ms], bl[0], bl[1]);
                    mma16(acc[ms][2 * nfp],     alf[ms], bh[0], bh[1]);
                    mma16(acc[ms][2 * nfp + 1], ahf[ms], bh[2], bh[3]);
                    mma16(acc[ms][2 * nfp + 1], ahf[ms], bl[2], bl[3]);
                    mma16(acc[ms][2 * nfp + 1], alf[ms], bh[2], bh[3]);
                }
            }
        }
        __syncthreads();
    }
#undef COPY_STAGE

    // ---- epilogue: accumulators -> smem Z-tile (alias over stage buffers) ----
    float* Zs = (float*)smw;          // [64][ZPITCH]
    // (last math phase done; the trailing __syncthreads above protects aliasing)
#pragma unroll
    for (int ms = 0; ms < 2; ms++) {
        int r = wm * 32 + ms * 16 + (lane >> 2);
#pragma unroll
        for (int nf = 0; nf < 4; nf++) {
            int jc = wn * 32 + nf * 8 + 2 * (lane & 3);
            Zs[r * ZPITCH + jc]           = acc[ms][nf][0];
            Zs[r * ZPITCH + jc + 1]       = acc[ms][nf][1];
            Zs[(r + 8) * ZPITCH + jc]     = acc[ms][nf][2];
            Zs[(r + 8) * ZPITCH + jc + 1] = acc[ms][nf][3];
        }
    }
    __syncthreads();

    // ---- pooling: 60 items = 20 o-groups x 3 conv types ----
    if (tid < 60) {
        int o_l = tid / 3, cv = tid % 3;
        int o_g = tileN * 20 + o_l;
        if (o_g < 100) {
            int cb = o_l * 6;
            float bias = (cv == 0) ? cb1[o_g] : (cv == 1 ? cb2[o_g] : cb3[o_g]);
            float mx = 0.f;          // relu floor
            int k = cv + 1;
            int tmax = min(64 - k, len - k - m0);   // t_local <= this
            if (cv == 0) {
                for (int t = 0; t <= tmax; t++)
                    mx = fmaxf(mx, Zs[t * ZPITCH + cb] + bias);
            } else if (cv == 1) {
                for (int t = 0; t <= tmax; t++)
                    mx = fmaxf(mx, Zs[t * ZPITCH + cb + 1] + Zs[(t + 1) * ZPITCH + cb + 2] + bias);
            } else {
                for (int t = 0; t <= tmax; t++)
                    mx = fmaxf(mx, Zs[t * ZPITCH + cb + 3] + Zs[(t + 1) * ZPITCH + cb + 4]
                                 + Zs[(t + 2) * ZPITCH + cb + 5] + bias);
            }
            int fidx = b * NCH + side * 300 + cv * 100 + o_g;
            atomicMax((int*)&g_feats[fidx], __float_as_int(mx));
        }
    }
}

// ---------------- dense head ----------------
__global__ void dense_kernel(const float* __restrict__ dw1, const float* __restrict__ db1,
                             const float* __restrict__ dw2, const float* __restrict__ db2,
                             float* __restrict__ out) {
    int b = blockIdx.x;
    __shared__ float f[NCH];
    __shared__ float h[64];
    int tid = threadIdx.x;
    for (int j = tid; j < NCH; j += blockDim.x) f[j] = g_feats[(size_t)b * NCH + j];
    __syncthreads();
    if (tid < 60) {
        float s = db1[tid];
        for (int j = 0; j < NCH; j++) s += f[j] * dw1[j * 60 + tid];
        h[tid] = fmaxf(s, 0.f);
    }
    __syncthreads();
    if (tid < 2) {
        float s = db2[tid];
        for (int j = 0; j < 60; j++) s += h[j] * dw2[j * 2 + tid];
        out[b * 2 + tid] = s;
    }
}

// ---------------- launch ----------------
extern "C" void kernel_launch(void* const* d_in, const int* in_sizes, int n_in,
                              void* d_out, int out_size) {
    const int*   lt   = (const int*)d_in[0];
    const int*   la   = (const int*)d_in[1];
    const int*   ll   = (const int*)d_in[2];
    const int*   rt   = (const int*)d_in[3];
    const int*   ra   = (const int*)d_in[4];
    const int*   rl   = (const int*)d_in[5];
    const float* wemb = (const float*)d_in[6];
    const float* aemb = (const float*)d_in[7];
    const float* cw1  = (const float*)d_in[8];
    const float* cb1  = (const float*)d_in[9];
    const float* cw2  = (const float*)d_in[10];
    const float* cb2  = (const float*)d_in[11];
    const float* cw3  = (const float*)d_in[12];
    const float* cb3  = (const float*)d_in[13];
    const float* dw1  = (const float*)d_in[14];
    const float* db1  = (const float*)d_in[15];
    const float* dw2  = (const float*)d_in[16];
    const float* db2  = (const float*)d_in[17];
    float* out = (float*)d_out;

    const int convSmem = STG_W * 4 * 2;   // 61440 bytes (Z-tile aliases inside)
    cudaFuncSetAttribute(conv_gemm_kernel,
                         cudaFuncAttributeMaxDynamicSharedMemorySize, convSmem);

    feats_init_kernel<<<(BSZ * NCH + 1023) / 1024, 1024>>>();
    prep_wall_kernel<<<(NPAD * DPW + 255) / 256, 256>>>(cw1, cw2, cw3);
    gather_kernel<<<dim3(LSZ, BSZ, 2), 96>>>(lt, la, rt, ra, wemb, aemb);
    att_gemm_kernel<<<dim3(3, 3, BSZ), 256>>>(ll, rl);
    attproc_kernel<<<dim3((BSZ * LSZ) / 4, 2), 128>>>(ll, rl);
    conv_gemm_kernel<<<dim3(3, 5, 2 * BSZ), 256, convSmem>>>(ll, rl, cb1, cb2, cb3);
    dense_kernel<<<BSZ, 128>>>(dw1, db1, dw2, db2, out);
}